// round 2
// baseline (speedup 1.0000x reference)
#include <cuda_runtime.h>
#include <math.h>

// ---------------- problem constants ----------------
#define TLEN 1024
#define DIMP 1024
#define DIN  2048            // D_INNER
#define NSTATE 16
#define TSUM (1024+512+256)  // 1792

// ---------------- scratch (device globals; no allocs allowed) ----------------
__device__ float g_xz   [TLEN*4096];
__device__ float g_x1   [512*DIN];
__device__ float g_x2   [256*DIN];
__device__ float g_xc   [TSUM*DIN];
__device__ float g_proj [TSUM*32];
__device__ float g_dt   [TSUM*DIN];
__device__ float g_y    [TSUM*DIN];
__device__ float g_fused[TLEN*DIN];
__device__ float g_ctx  [TLEN*DIN];
__device__ float g_g1   [TLEN*DIMP];
__device__ float g_gc   [TLEN*DIN];
__device__ float g_pre  [TLEN*DIN];
__device__ float g_yres [TLEN*DIMP];

// ---------------- helpers ----------------
__device__ __forceinline__ float sigmoidf_(float x) { return 1.0f / (1.0f + expf(-x)); }
__device__ __forceinline__ float siluf_(float x)    { return x / (1.0f + expf(-x)); }
__device__ __forceinline__ float softplusf_(float x) {
    // stable: max(x,0) + log1p(exp(-|x|))  (matches jax.nn.softplus)
    return fmaxf(x, 0.0f) + log1pf(expf(-fabsf(x)));
}

// ---------------- generic SGEMM: C[M,N] = A[M,K] * B[N,K]^T (+ epilogue) ------
// EPI: 0 = none, 1 = silu, 2 = sigmoid, 3 = add residual (Res[M,N])
// Requires M,N multiples of 128, K multiple of 8. 256 threads.
template<int EPI>
__global__ __launch_bounds__(256)
void sgemm_tn(const float* __restrict__ A, const float* __restrict__ B,
              float* __restrict__ C, const float* __restrict__ Res,
              int M, int N, int K)
{
    const int BM = 128, BN = 128, BK = 8;
    __shared__ float As[BK][BM];
    __shared__ float Bs[BK][BN];

    const int bm = blockIdx.y * BM;
    const int bn = blockIdx.x * BN;
    const int tid  = threadIdx.x;
    const int warp = tid >> 5;
    const int lane = tid & 31;
    // warp grid 2x4 (64x32 per warp); lane grid 8x4 (8x8 per thread)
    const int wm = (warp >> 2) * 64;
    const int wn = (warp & 3) * 32;
    const int lm = (lane >> 2) * 8;
    const int ln = (lane & 3) * 8;
    const int row0 = bm + wm + lm;    // first of 8 output rows
    const int col0 = bn + wn + ln;    // first of 8 output cols

    // tile load mapping: each thread loads one float4 of A and one of B
    const int lrow = tid >> 1;        // 0..127
    const int lk4  = (tid & 1) * 4;   // 0 or 4
    const float* Ald = A + (size_t)(bm + lrow) * K + lk4;
    const float* Bld = B + (size_t)(bn + lrow) * K + lk4;

    float acc[8][8];
#pragma unroll
    for (int i = 0; i < 8; i++)
#pragma unroll
        for (int j = 0; j < 8; j++) acc[i][j] = 0.0f;

    for (int k0 = 0; k0 < K; k0 += BK) {
        float4 av = *(const float4*)(Ald + k0);
        float4 bv = *(const float4*)(Bld + k0);
        As[lk4 + 0][lrow] = av.x; As[lk4 + 1][lrow] = av.y;
        As[lk4 + 2][lrow] = av.z; As[lk4 + 3][lrow] = av.w;
        Bs[lk4 + 0][lrow] = bv.x; Bs[lk4 + 1][lrow] = bv.y;
        Bs[lk4 + 2][lrow] = bv.z; Bs[lk4 + 3][lrow] = bv.w;
        __syncthreads();

#pragma unroll
        for (int k = 0; k < BK; k++) {
            float a[8], b[8];
            *(float4*)(a)     = *(const float4*)&As[k][wm + lm];
            *(float4*)(a + 4) = *(const float4*)&As[k][wm + lm + 4];
            *(float4*)(b)     = *(const float4*)&Bs[k][wn + ln];
            *(float4*)(b + 4) = *(const float4*)&Bs[k][wn + ln + 4];
#pragma unroll
            for (int i = 0; i < 8; i++)
#pragma unroll
                for (int j = 0; j < 8; j++)
                    acc[i][j] = fmaf(a[i], b[j], acc[i][j]);
        }
        __syncthreads();
    }

#pragma unroll
    for (int i = 0; i < 8; i++) {
        const size_t r = (size_t)(row0 + i) * N + col0;
        float v[8];
#pragma unroll
        for (int j = 0; j < 8; j++) {
            float x = acc[i][j];
            if (EPI == 1) x = siluf_(x);
            else if (EPI == 2) x = sigmoidf_(x);
            else if (EPI == 3) x = x + Res[r + j];
            v[j] = x;
        }
        *(float4*)(C + r)     = *(float4*)(v);
        *(float4*)(C + r + 4) = *(float4*)(v + 4);
    }
}

// ---------------- downsample (mean over stride) from x_in = g_xz[:, :2048] ----
__global__ void down2_kernel(const float* __restrict__ xz, float* __restrict__ o)
{
    int idx = blockIdx.x * blockDim.x + threadIdx.x;     // 512*2048
    int t = idx >> 11, d = idx & 2047;
    o[idx] = 0.5f * (xz[(size_t)(2 * t) * 4096 + d] + xz[(size_t)(2 * t + 1) * 4096 + d]);
}
__global__ void down4_kernel(const float* __restrict__ xz, float* __restrict__ o)
{
    int idx = blockIdx.x * blockDim.x + threadIdx.x;     // 256*2048
    int t = idx >> 11, d = idx & 2047;
    float s = xz[(size_t)(4 * t) * 4096 + d] + xz[(size_t)(4 * t + 1) * 4096 + d]
            + xz[(size_t)(4 * t + 2) * 4096 + d] + xz[(size_t)(4 * t + 3) * 4096 + d];
    o[idx] = 0.25f * s;
}

// ---------------- causal depthwise conv (K=4) + silu ----------------
__global__ void conv_silu_kernel(const float* __restrict__ x, int xs,
                                 const float* __restrict__ w, const float* __restrict__ b,
                                 float* __restrict__ xc, int T)
{
    int idx = blockIdx.x * blockDim.x + threadIdx.x;   // T*2048
    int t = idx >> 11, d = idx & 2047;
    float4 wv = *(const float4*)(w + d * 4);
    float acc = b[d];
    if (t >= 3) acc = fmaf(x[(size_t)(t - 3) * xs + d], wv.x, acc);
    if (t >= 2) acc = fmaf(x[(size_t)(t - 2) * xs + d], wv.y, acc);
    if (t >= 1) acc = fmaf(x[(size_t)(t - 1) * xs + d], wv.z, acc);
    acc = fmaf(x[(size_t)t * xs + d], wv.w, acc);
    xc[(size_t)t * DIN + d] = acc * sigmoidf_(acc);
}

// ---------------- xproj: proj[T,32] = xc[T,2048] @ xw[32,2048]^T --------------
// one block per t; 8 warps, each warp does 4 outputs with coalesced K loop
__global__ __launch_bounds__(256)
void xproj_kernel(const float* __restrict__ xc, const float* __restrict__ xw,
                  float* __restrict__ proj)
{
    int t = blockIdx.x;
    int warp = threadIdx.x >> 5, lane = threadIdx.x & 31;
    const float* xr = xc + (size_t)t * DIN;
    float acc0 = 0, acc1 = 0, acc2 = 0, acc3 = 0;
    const float* w0 = xw + (size_t)(warp * 4 + 0) * DIN;
    const float* w1 = xw + (size_t)(warp * 4 + 1) * DIN;
    const float* w2 = xw + (size_t)(warp * 4 + 2) * DIN;
    const float* w3 = xw + (size_t)(warp * 4 + 3) * DIN;
    for (int k = lane; k < DIN; k += 32) {
        float xv = xr[k];
        acc0 = fmaf(xv, w0[k], acc0);
        acc1 = fmaf(xv, w1[k], acc1);
        acc2 = fmaf(xv, w2[k], acc2);
        acc3 = fmaf(xv, w3[k], acc3);
    }
#pragma unroll
    for (int o = 16; o > 0; o >>= 1) {
        acc0 += __shfl_xor_sync(0xffffffffu, acc0, o);
        acc1 += __shfl_xor_sync(0xffffffffu, acc1, o);
        acc2 += __shfl_xor_sync(0xffffffffu, acc2, o);
        acc3 += __shfl_xor_sync(0xffffffffu, acc3, o);
    }
    if (lane == 0) {
        proj[t * 32 + warp * 4 + 0] = acc0;
        proj[t * 32 + warp * 4 + 1] = acc1;
        proj[t * 32 + warp * 4 + 2] = acc2;
        proj[t * 32 + warp * 4 + 3] = acc3;
    }
}

// ---------------- dt = softplus(softplus(B @ dtw^T + dtb)) --------------------
__global__ void dt_kernel(const float* __restrict__ proj, const float* __restrict__ dtw,
                          const float* __restrict__ dtb, float* __restrict__ dt)
{
    int t  = blockIdx.x >> 3;
    int d  = ((blockIdx.x & 7) << 8) + threadIdx.x;
    __shared__ float Bs[16];
    if (threadIdx.x < 16) Bs[threadIdx.x] = proj[t * 32 + threadIdx.x];
    __syncthreads();
    const float4* wp = (const float4*)(dtw + (size_t)d * 16);
    float4 w0 = wp[0], w1 = wp[1], w2 = wp[2], w3 = wp[3];
    float acc = dtb[d];
    acc = fmaf(Bs[0],  w0.x, acc); acc = fmaf(Bs[1],  w0.y, acc);
    acc = fmaf(Bs[2],  w0.z, acc); acc = fmaf(Bs[3],  w0.w, acc);
    acc = fmaf(Bs[4],  w1.x, acc); acc = fmaf(Bs[5],  w1.y, acc);
    acc = fmaf(Bs[6],  w1.z, acc); acc = fmaf(Bs[7],  w1.w, acc);
    acc = fmaf(Bs[8],  w2.x, acc); acc = fmaf(Bs[9],  w2.y, acc);
    acc = fmaf(Bs[10], w2.z, acc); acc = fmaf(Bs[11], w2.w, acc);
    acc = fmaf(Bs[12], w3.x, acc); acc = fmaf(Bs[13], w3.y, acc);
    acc = fmaf(Bs[14], w3.z, acc);  acc = fmaf(Bs[15], w3.w, acc);
    dt[(size_t)t * DIN + d] = softplusf_(softplusf_(acc));
}

// ---------------- selective scan + C contraction ------------------------------
// thread = (channel d, state s); 16-lane shuffle reduce for y[t,d] = sum_s C*h
// Recurrence (exactly equals the reference's log-domain formulation):
//   h[t] = max(exp(-dt*(s+1)), 1e-38) * h[t-1] + max(dt*B*xc, 1e-38)
__global__ __launch_bounds__(256)
void scan_kernel(const float* __restrict__ dt, const float* __restrict__ xc,
                 const float* __restrict__ proj, const float* __restrict__ Dp,
                 float* __restrict__ y, int T)
{
    int gid = blockIdx.x * blockDim.x + threadIdx.x;   // 32768
    int d = gid >> 4;
    int s = gid & 15;
    const float A = -(float)(s + 1);
    const float Dd = Dp[d];
    float h = 0.0f;
    for (int t = 0; t < T; t++) {
        float dtv = dt[(size_t)t * DIN + d];
        float xcv = xc[(size_t)t * DIN + d];
        float Bv  = proj[t * 32 + s];
        float Cv  = proj[t * 32 + 16 + s];
        float da  = fmaxf(expf(dtv * A), 1e-38f);
        float dbx = fmaxf(dtv * Bv * xcv, 1e-38f);
        h = fmaf(da, h, dbx);
        float v = Cv * h;
        v += __shfl_xor_sync(0xffffffffu, v, 8, 16);
        v += __shfl_xor_sync(0xffffffffu, v, 4, 16);
        v += __shfl_xor_sync(0xffffffffu, v, 2, 16);
        v += __shfl_xor_sync(0xffffffffu, v, 1, 16);
        if (s == 0) y[(size_t)t * DIN + d] = v + Dd * xcv;
    }
}

// ---------------- upsample + softmax-weighted fuse + ctx ----------------------
__global__ void fuse_kernel(const float* __restrict__ y0, const float* __restrict__ y1,
                            const float* __restrict__ y2, const float* __restrict__ sw,
                            float* __restrict__ fused, float* __restrict__ ctx)
{
    int idx = blockIdx.x * blockDim.x + threadIdx.x;   // 1024*2048
    int t = idx >> 11, d = idx & 2047;

    float o0 = y0[idx];

    float p1 = fminf(fmaxf(0.5f * (float)t - 0.25f, 0.0f), 511.0f);
    int lo1 = (int)floorf(p1);
    int hi1 = min(lo1 + 1, 511);
    float w1 = p1 - (float)lo1;
    float o1 = y1[(size_t)lo1 * DIN + d] * (1.0f - w1) + y1[(size_t)hi1 * DIN + d] * w1;

    float p2 = fminf(fmaxf(0.25f * (float)t - 0.375f, 0.0f), 255.0f);
    int lo2 = (int)floorf(p2);
    int hi2 = min(lo2 + 1, 255);
    float w2 = p2 - (float)lo2;
    float o2 = y2[(size_t)lo2 * DIN + d] * (1.0f - w2) + y2[(size_t)hi2 * DIN + d] * w2;

    float s0 = sw[0], s1 = sw[1], s2 = sw[2];
    float m = fmaxf(s0, fmaxf(s1, s2));
    float e0 = expf(s0 - m), e1 = expf(s1 - m), e2 = expf(s2 - m);
    float inv = 1.0f / (e0 + e1 + e2);

    fused[idx] = e0 * inv * o0 + e1 * inv * o1 + e2 * inv * o2;
    ctx[idx]   = (o0 + o1 + o2) * (1.0f / 3.0f);
}

// ---------------- pre = fused * gate_ctx * silu(gate) -------------------------
__global__ void pre_kernel(const float* __restrict__ fused, const float* __restrict__ gc,
                           const float* __restrict__ xz, float* __restrict__ pre)
{
    int idx = blockIdx.x * blockDim.x + threadIdx.x;   // 1024*2048
    int t = idx >> 11, d = idx & 2047;
    float gv = xz[(size_t)t * 4096 + 2048 + d];
    pre[idx] = fused[idx] * gc[idx] * siluf_(gv);
}

// ---------------- layernorm over last dim (1024) ------------------------------
__global__ __launch_bounds__(256)
void ln_kernel(const float* __restrict__ y, const float* __restrict__ g,
               const float* __restrict__ b, float* __restrict__ out)
{
    int t = blockIdx.x;
    const float* yr = y + (size_t)t * DIMP;
    float vals[4];
    float s = 0.0f, s2 = 0.0f;
#pragma unroll
    for (int i = 0; i < 4; i++) {
        float v = yr[threadIdx.x + i * 256];
        vals[i] = v; s += v; s2 += v * v;
    }
#pragma unroll
    for (int o = 16; o > 0; o >>= 1) {
        s  += __shfl_xor_sync(0xffffffffu, s, o);
        s2 += __shfl_xor_sync(0xffffffffu, s2, o);
    }
    __shared__ float rs[8], rs2[8];
    int warp = threadIdx.x >> 5, lane = threadIdx.x & 31;
    if (lane == 0) { rs[warp] = s; rs2[warp] = s2; }
    __syncthreads();
    if (threadIdx.x == 0) {
        float S = 0, S2 = 0;
#pragma unroll
        for (int i = 0; i < 8; i++) { S += rs[i]; S2 += rs2[i]; }
        rs[0] = S; rs2[0] = S2;
    }
    __syncthreads();
    float mu  = rs[0] * (1.0f / 1024.0f);
    float var = rs2[0] * (1.0f / 1024.0f) - mu * mu;
    float rstd = rsqrtf(var + 1e-5f);
#pragma unroll
    for (int i = 0; i < 4; i++) {
        int j = threadIdx.x + i * 256;
        out[(size_t)t * DIMP + j] = (vals[i] - mu) * rstd * g[j] + b[j];
    }
}

// ---------------- launch ------------------------------------------------------
extern "C" void kernel_launch(void* const* d_in, const int* in_sizes, int n_in,
                              void* d_out, int out_size)
{
    const float* x          = (const float*)d_in[0];
    const float* in_proj_w  = (const float*)d_in[1];
    const float* conv_w     = (const float*)d_in[2];
    const float* conv_b     = (const float*)d_in[3];
    const float* xproj_w    = (const float*)d_in[4];
    const float* dtproj_w   = (const float*)d_in[5];
    const float* dtproj_b   = (const float*)d_in[6];
    const float* D_param    = (const float*)d_in[7];
    const float* scale_w    = (const float*)d_in[8];
    const float* gate_w1    = (const float*)d_in[9];
    const float* gate_w2    = (const float*)d_in[10];
    const float* out_proj_w = (const float*)d_in[11];
    const float* ln_g       = (const float*)d_in[12];
    const float* ln_b       = (const float*)d_in[13];
    float* out = (float*)d_out;

    float *xz, *x1, *x2, *xc, *proj, *dt, *yb, *fused, *ctx, *g1, *gc, *pre, *yres;
    cudaGetSymbolAddress((void**)&xz,   g_xz);
    cudaGetSymbolAddress((void**)&x1,   g_x1);
    cudaGetSymbolAddress((void**)&x2,   g_x2);
    cudaGetSymbolAddress((void**)&xc,   g_xc);
    cudaGetSymbolAddress((void**)&proj, g_proj);
    cudaGetSymbolAddress((void**)&dt,   g_dt);
    cudaGetSymbolAddress((void**)&yb,   g_y);
    cudaGetSymbolAddress((void**)&fused,g_fused);
    cudaGetSymbolAddress((void**)&ctx,  g_ctx);
    cudaGetSymbolAddress((void**)&g1,   g_g1);
    cudaGetSymbolAddress((void**)&gc,   g_gc);
    cudaGetSymbolAddress((void**)&pre,  g_pre);
    cudaGetSymbolAddress((void**)&yres, g_yres);

    // 1) xz = x @ in_proj_w^T   [1024,4096]
    sgemm_tn<0><<<dim3(4096 / 128, 1024 / 128), 256>>>(x, in_proj_w, xz, nullptr, 1024, 4096, 1024);

    // 2) downsample x_in
    down2_kernel<<<(512 * DIN) / 256, 256>>>(xz, x1);
    down4_kernel<<<(256 * DIN) / 256, 256>>>(xz, x2);

    // 3) per-scale SSM pipeline
    const int   Ts[3]     = {1024, 512, 256};
    const int   toff[3]   = {0, 1024, 1536};
    const int   xstr[3]   = {4096, DIN, DIN};
    const float* xs[3]; xs[0] = xz; xs[1] = x1; xs[2] = x2;

    for (int s = 0; s < 3; s++) {
        float* xc_s   = xc   + (size_t)toff[s] * DIN;
        float* proj_s = proj + (size_t)toff[s] * 32;
        float* dt_s   = dt   + (size_t)toff[s] * DIN;
        float* y_s    = yb   + (size_t)toff[s] * DIN;

        conv_silu_kernel<<<(Ts[s] * DIN) / 256, 256>>>(
            xs[s], xstr[s], conv_w + (size_t)s * DIN * 4, conv_b + (size_t)s * DIN, xc_s, Ts[s]);
        xproj_kernel<<<Ts[s], 256>>>(xc_s, xproj_w + (size_t)s * 32 * DIN, proj_s);
        dt_kernel<<<Ts[s] * 8, 256>>>(proj_s, dtproj_w + (size_t)s * DIN * 16,
                                      dtproj_b + (size_t)s * DIN, dt_s);
        scan_kernel<<<(DIN * NSTATE) / 256, 256>>>(dt_s, xc_s, proj_s,
                                                   D_param + (size_t)s * DIN, y_s, Ts[s]);
    }

    // 4) upsample + fuse + ctx
    fuse_kernel<<<(TLEN * DIN) / 256, 256>>>(yb, yb + (size_t)1024 * DIN, yb + (size_t)1536 * DIN,
                                             scale_w, fused, ctx);

    // 5) gating network
    sgemm_tn<1><<<dim3(1024 / 128, 1024 / 128), 256>>>(ctx, gate_w1, g1, nullptr, 1024, 1024, 2048);
    sgemm_tn<2><<<dim3(2048 / 128, 1024 / 128), 256>>>(g1, gate_w2, gc, nullptr, 1024, 2048, 1024);

    // 6) pre = fused * gate_ctx * silu(gate)
    pre_kernel<<<(TLEN * DIN) / 256, 256>>>(fused, gc, xz, pre);

    // 7) out_proj + residual
    sgemm_tn<3><<<dim3(1024 / 128, 1024 / 128), 256>>>(pre, out_proj_w, yres, x, 1024, 1024, 2048);

    // 8) layernorm -> output
    ln_kernel<<<1024, 256>>>(yres, ln_g, ln_b, out);
}

// round 4
// speedup vs baseline: 1.6255x; 1.6255x over previous
#include <cuda_runtime.h>
#include <cuda_bf16.h>
#include <math.h>
#include <stdint.h>

// ---------------- problem constants ----------------
#define TLEN 1024
#define DIMP 1024
#define DIN  2048            // D_INNER
#define NSTATE 16
#define TSUM (1024+512+256)  // 1792

// ---------------- scratch (device globals; no allocs allowed) ----------------
__device__ float g_xz   [TLEN*4096];
__device__ float g_x1   [512*DIN];
__device__ float g_x2   [256*DIN];
__device__ float g_xc   [TSUM*DIN];
__device__ float g_proj [TSUM*32];
__device__ float g_dt   [TSUM*DIN];
__device__ float g_y    [TSUM*DIN];
__device__ float g_fused[TLEN*DIN];
__device__ float g_ctx  [TLEN*DIN];
__device__ float g_g1   [TLEN*DIMP];
__device__ float g_gc   [TLEN*DIN];
__device__ float g_pre  [TLEN*DIN];
__device__ float g_yres [TLEN*DIMP];

// ---------------- helpers ----------------
__device__ __forceinline__ float sigmoidf_(float x) { return 1.0f / (1.0f + expf(-x)); }
__device__ __forceinline__ float siluf_(float x)    { return x / (1.0f + expf(-x)); }
__device__ __forceinline__ float softplusf_(float x) {
    return fmaxf(x, 0.0f) + log1pf(expf(-fabsf(x)));
}

// ============ tensor-core GEMM via mma.sync (bf16 hi/lo split) ===============
// C[M,N] = A[M,K] @ B[N,K]^T, fp32 in/out.
// fp32 -> bf16 hi + bf16 lo(residual); C ~= Ah*Bh + Ah*Bl + Al*Bh (3 passes).
// CTA tile 128x128, BK=32, 8 warps (2x4), warp tile 64x32, m16n8k16.
// EPI: 0 none, 1 silu, 2 sigmoid, 3 +Res

#define MMA_BF16(c, a, b) \
  asm volatile("mma.sync.aligned.m16n8k16.row.col.f32.bf16.bf16.f32 " \
      "{%0,%1,%2,%3}, {%4,%5,%6,%7}, {%8,%9}, {%0,%1,%2,%3};" \
      : "+f"((c)[0]), "+f"((c)[1]), "+f"((c)[2]), "+f"((c)[3]) \
      : "r"((a)[0]), "r"((a)[1]), "r"((a)[2]), "r"((a)[3]), \
        "r"((b)[0]), "r"((b)[1]))

#define GPAD 40   // bf16 elements per smem row (32 data + 8 pad) -> conflict-free

__device__ __forceinline__ void cvt_store_hilo(__nv_bfloat16* hi, __nv_bfloat16* lo,
                                               int off, float4 v)
{
    __nv_bfloat162 h01 = __floats2bfloat162_rn(v.x, v.y);
    __nv_bfloat162 h23 = __floats2bfloat162_rn(v.z, v.w);
    float2 f01 = __bfloat1622float2(h01);
    float2 f23 = __bfloat1622float2(h23);
    __nv_bfloat162 l01 = __floats2bfloat162_rn(v.x - f01.x, v.y - f01.y);
    __nv_bfloat162 l23 = __floats2bfloat162_rn(v.z - f23.x, v.w - f23.y);
    uint2 hv, lv;
    hv.x = *(uint32_t*)&h01; hv.y = *(uint32_t*)&h23;
    lv.x = *(uint32_t*)&l01; lv.y = *(uint32_t*)&l23;
    *(uint2*)&hi[off] = hv;
    *(uint2*)&lo[off] = lv;
}

template<int EPI>
__global__ __launch_bounds__(256, 2)
void gemm_mma(const float* __restrict__ A, const float* __restrict__ B,
              float* __restrict__ C, const float* __restrict__ Res,
              int M, int N, int K)
{
    __shared__ __nv_bfloat16 sAhi[128 * GPAD];
    __shared__ __nv_bfloat16 sAlo[128 * GPAD];
    __shared__ __nv_bfloat16 sBhi[128 * GPAD];
    __shared__ __nv_bfloat16 sBlo[128 * GPAD];

    const int tid  = threadIdx.x;
    const int warp = tid >> 5;
    const int lane = tid & 31;
    const int g    = lane >> 2;       // group id (0..7)
    const int tig  = lane & 3;        // thread in group
    const int wm   = (warp >> 2) * 64;
    const int wn   = (warp & 3) * 32;
    const int bm   = blockIdx.y * 128;
    const int bn   = blockIdx.x * 128;
    const int K4   = K >> 2;

    float acc[4][4][4];
#pragma unroll
    for (int mi = 0; mi < 4; mi++)
#pragma unroll
        for (int ni = 0; ni < 4; ni++)
#pragma unroll
            for (int q = 0; q < 4; q++) acc[mi][ni][q] = 0.0f;

    for (int k0 = 0; k0 < K; k0 += 32) {
        // ---- stage tiles: 128x32 fp32 -> hi/lo bf16 (4 float4 per thread each) ----
        {
            const float4* Ap = (const float4*)(A + (size_t)bm * K + k0);
            const float4* Bp = (const float4*)(B + (size_t)bn * K + k0);
#pragma unroll
            for (int i = 0; i < 4; i++) {
                int idx = tid + i * 256;          // 0..1023
                int row = idx >> 3;
                int c4  = (idx & 7) << 2;         // k offset within 32
                float4 va = Ap[(size_t)row * K4 + (c4 >> 2)];
                cvt_store_hilo(sAhi, sAlo, row * GPAD + c4, va);
                float4 vb = Bp[(size_t)row * K4 + (c4 >> 2)];
                cvt_store_hilo(sBhi, sBlo, row * GPAD + c4, vb);
            }
        }
        __syncthreads();

#pragma unroll
        for (int ks = 0; ks < 32; ks += 16) {
            const int ak = ks + tig * 2;
            uint32_t ahi[4][4], bhi[4][2];
#pragma unroll
            for (int mi = 0; mi < 4; mi++) {
                int r0 = wm + mi * 16 + g;
                ahi[mi][0] = *(const uint32_t*)&sAhi[(r0    ) * GPAD + ak];
                ahi[mi][1] = *(const uint32_t*)&sAhi[(r0 + 8) * GPAD + ak];
                ahi[mi][2] = *(const uint32_t*)&sAhi[(r0    ) * GPAD + ak + 8];
                ahi[mi][3] = *(const uint32_t*)&sAhi[(r0 + 8) * GPAD + ak + 8];
            }
#pragma unroll
            for (int ni = 0; ni < 4; ni++) {
                int c0 = wn + ni * 8 + g;
                bhi[ni][0] = *(const uint32_t*)&sBhi[c0 * GPAD + ak];
                bhi[ni][1] = *(const uint32_t*)&sBhi[c0 * GPAD + ak + 8];
            }
            // pass 1: Ah * Bh
#pragma unroll
            for (int mi = 0; mi < 4; mi++)
#pragma unroll
                for (int ni = 0; ni < 4; ni++)
                    MMA_BF16(acc[mi][ni], ahi[mi], bhi[ni]);
            // pass 2: Ah * Bl
            {
                uint32_t blo[4][2];
#pragma unroll
                for (int ni = 0; ni < 4; ni++) {
                    int c0 = wn + ni * 8 + g;
                    blo[ni][0] = *(const uint32_t*)&sBlo[c0 * GPAD + ak];
                    blo[ni][1] = *(const uint32_t*)&sBlo[c0 * GPAD + ak + 8];
                }
#pragma unroll
                for (int mi = 0; mi < 4; mi++)
#pragma unroll
                    for (int ni = 0; ni < 4; ni++)
                        MMA_BF16(acc[mi][ni], ahi[mi], blo[ni]);
            }
            // pass 3: Al * Bh
            {
                uint32_t alo[4][4];
#pragma unroll
                for (int mi = 0; mi < 4; mi++) {
                    int r0 = wm + mi * 16 + g;
                    alo[mi][0] = *(const uint32_t*)&sAlo[(r0    ) * GPAD + ak];
                    alo[mi][1] = *(const uint32_t*)&sAlo[(r0 + 8) * GPAD + ak];
                    alo[mi][2] = *(const uint32_t*)&sAlo[(r0    ) * GPAD + ak + 8];
                    alo[mi][3] = *(const uint32_t*)&sAlo[(r0 + 8) * GPAD + ak + 8];
                }
#pragma unroll
                for (int mi = 0; mi < 4; mi++)
#pragma unroll
                    for (int ni = 0; ni < 4; ni++)
                        MMA_BF16(acc[mi][ni], alo[mi], bhi[ni]);
            }
        }
        __syncthreads();
    }

    // ---- epilogue ----
#pragma unroll
    for (int mi = 0; mi < 4; mi++) {
        int row = bm + wm + mi * 16 + g;
#pragma unroll
        for (int ni = 0; ni < 4; ni++) {
            int col = bn + wn + ni * 8 + tig * 2;
            float v0 = acc[mi][ni][0], v1 = acc[mi][ni][1];
            float v2 = acc[mi][ni][2], v3 = acc[mi][ni][3];
            if (EPI == 1) { v0 = siluf_(v0); v1 = siluf_(v1); v2 = siluf_(v2); v3 = siluf_(v3); }
            else if (EPI == 2) { v0 = sigmoidf_(v0); v1 = sigmoidf_(v1); v2 = sigmoidf_(v2); v3 = sigmoidf_(v3); }
            else if (EPI == 3) {
                const float2 r0v = *(const float2*)(Res + (size_t)row * N + col);
                const float2 r1v = *(const float2*)(Res + (size_t)(row + 8) * N + col);
                v0 += r0v.x; v1 += r0v.y; v2 += r1v.x; v3 += r1v.y;
            }
            float2 o0; o0.x = v0; o0.y = v1;
            float2 o1; o1.x = v2; o1.y = v3;
            *(float2*)(C + (size_t)row * N + col)       = o0;
            *(float2*)(C + (size_t)(row + 8) * N + col) = o1;
        }
    }
}

// ---------------- downsample ----------------
__global__ void down2_kernel(const float* __restrict__ xz, float* __restrict__ o)
{
    int idx = blockIdx.x * blockDim.x + threadIdx.x;
    int t = idx >> 11, d = idx & 2047;
    o[idx] = 0.5f * (xz[(size_t)(2 * t) * 4096 + d] + xz[(size_t)(2 * t + 1) * 4096 + d]);
}
__global__ void down4_kernel(const float* __restrict__ xz, float* __restrict__ o)
{
    int idx = blockIdx.x * blockDim.x + threadIdx.x;
    int t = idx >> 11, d = idx & 2047;
    float s = xz[(size_t)(4 * t) * 4096 + d] + xz[(size_t)(4 * t + 1) * 4096 + d]
            + xz[(size_t)(4 * t + 2) * 4096 + d] + xz[(size_t)(4 * t + 3) * 4096 + d];
    o[idx] = 0.25f * s;
}

// ---------------- causal depthwise conv (K=4) + silu ----------------
__global__ void conv_silu_kernel(const float* __restrict__ x, int xs,
                                 const float* __restrict__ w, const float* __restrict__ b,
                                 float* __restrict__ xc, int T)
{
    int idx = blockIdx.x * blockDim.x + threadIdx.x;
    int t = idx >> 11, d = idx & 2047;
    float4 wv = *(const float4*)(w + d * 4);
    float acc = b[d];
    if (t >= 3) acc = fmaf(x[(size_t)(t - 3) * xs + d], wv.x, acc);
    if (t >= 2) acc = fmaf(x[(size_t)(t - 2) * xs + d], wv.y, acc);
    if (t >= 1) acc = fmaf(x[(size_t)(t - 1) * xs + d], wv.z, acc);
    acc = fmaf(x[(size_t)t * xs + d], wv.w, acc);
    xc[(size_t)t * DIN + d] = acc * sigmoidf_(acc);
}

// ---------------- xproj ----------------
__global__ __launch_bounds__(256)
void xproj_kernel(const float* __restrict__ xc, const float* __restrict__ xw,
                  float* __restrict__ proj)
{
    int t = blockIdx.x;
    int warp = threadIdx.x >> 5, lane = threadIdx.x & 31;
    const float* xr = xc + (size_t)t * DIN;
    float acc0 = 0, acc1 = 0, acc2 = 0, acc3 = 0;
    const float* w0 = xw + (size_t)(warp * 4 + 0) * DIN;
    const float* w1 = xw + (size_t)(warp * 4 + 1) * DIN;
    const float* w2 = xw + (size_t)(warp * 4 + 2) * DIN;
    const float* w3 = xw + (size_t)(warp * 4 + 3) * DIN;
    for (int k = lane; k < DIN; k += 32) {
        float xv = xr[k];
        acc0 = fmaf(xv, w0[k], acc0);
        acc1 = fmaf(xv, w1[k], acc1);
        acc2 = fmaf(xv, w2[k], acc2);
        acc3 = fmaf(xv, w3[k], acc3);
    }
#pragma unroll
    for (int o = 16; o > 0; o >>= 1) {
        acc0 += __shfl_xor_sync(0xffffffffu, acc0, o);
        acc1 += __shfl_xor_sync(0xffffffffu, acc1, o);
        acc2 += __shfl_xor_sync(0xffffffffu, acc2, o);
        acc3 += __shfl_xor_sync(0xffffffffu, acc3, o);
    }
    if (lane == 0) {
        proj[t * 32 + warp * 4 + 0] = acc0;
        proj[t * 32 + warp * 4 + 1] = acc1;
        proj[t * 32 + warp * 4 + 2] = acc2;
        proj[t * 32 + warp * 4 + 3] = acc3;
    }
}

// ---------------- dt ----------------
__global__ void dt_kernel(const float* __restrict__ proj, const float* __restrict__ dtw,
                          const float* __restrict__ dtb, float* __restrict__ dt)
{
    int t  = blockIdx.x >> 3;
    int d  = ((blockIdx.x & 7) << 8) + threadIdx.x;
    __shared__ float Bs[16];
    if (threadIdx.x < 16) Bs[threadIdx.x] = proj[t * 32 + threadIdx.x];
    __syncthreads();
    const float4* wp = (const float4*)(dtw + (size_t)d * 16);
    float4 w0 = wp[0], w1 = wp[1], w2 = wp[2], w3 = wp[3];
    float acc = dtb[d];
    acc = fmaf(Bs[0],  w0.x, acc); acc = fmaf(Bs[1],  w0.y, acc);
    acc = fmaf(Bs[2],  w0.z, acc); acc = fmaf(Bs[3],  w0.w, acc);
    acc = fmaf(Bs[4],  w1.x, acc); acc = fmaf(Bs[5],  w1.y, acc);
    acc = fmaf(Bs[6],  w1.z, acc); acc = fmaf(Bs[7],  w1.w, acc);
    acc = fmaf(Bs[8],  w2.x, acc); acc = fmaf(Bs[9],  w2.y, acc);
    acc = fmaf(Bs[10], w2.z, acc); acc = fmaf(Bs[11], w2.w, acc);
    acc = fmaf(Bs[12], w3.x, acc); acc = fmaf(Bs[13], w3.y, acc);
    acc = fmaf(Bs[14], w3.z, acc); acc = fmaf(Bs[15], w3.w, acc);
    dt[(size_t)t * DIN + d] = softplusf_(softplusf_(acc));
}

// ---------------- selective scan ----------------
__global__ __launch_bounds__(256)
void scan_kernel(const float* __restrict__ dt, const float* __restrict__ xc,
                 const float* __restrict__ proj, const float* __restrict__ Dp,
                 float* __restrict__ y, int T)
{
    int gid = blockIdx.x * blockDim.x + threadIdx.x;
    int d = gid >> 4;
    int s = gid & 15;
    const float A = -(float)(s + 1);
    const float Dd = Dp[d];
    float h = 0.0f;
    for (int t = 0; t < T; t++) {
        float dtv = dt[(size_t)t * DIN + d];
        float xcv = xc[(size_t)t * DIN + d];
        float Bv  = proj[t * 32 + s];
        float Cv  = proj[t * 32 + 16 + s];
        float da  = fmaxf(expf(dtv * A), 1e-38f);
        float dbx = fmaxf(dtv * Bv * xcv, 1e-38f);
        h = fmaf(da, h, dbx);
        float v = Cv * h;
        v += __shfl_xor_sync(0xffffffffu, v, 8, 16);
        v += __shfl_xor_sync(0xffffffffu, v, 4, 16);
        v += __shfl_xor_sync(0xffffffffu, v, 2, 16);
        v += __shfl_xor_sync(0xffffffffu, v, 1, 16);
        if (s == 0) y[(size_t)t * DIN + d] = v + Dd * xcv;
    }
}

// ---------------- fuse ----------------
__global__ void fuse_kernel(const float* __restrict__ y0, const float* __restrict__ y1,
                            const float* __restrict__ y2, const float* __restrict__ sw,
                            float* __restrict__ fused, float* __restrict__ ctx)
{
    int idx = blockIdx.x * blockDim.x + threadIdx.x;
    int t = idx >> 11, d = idx & 2047;

    float o0 = y0[idx];

    float p1 = fminf(fmaxf(0.5f * (float)t - 0.25f, 0.0f), 511.0f);
    int lo1 = (int)floorf(p1);
    int hi1 = min(lo1 + 1, 511);
    float w1 = p1 - (float)lo1;
    float o1 = y1[(size_t)lo1 * DIN + d] * (1.0f - w1) + y1[(size_t)hi1 * DIN + d] * w1;

    float p2 = fminf(fmaxf(0.25f * (float)t - 0.375f, 0.0f), 255.0f);
    int lo2 = (int)floorf(p2);
    int hi2 = min(lo2 + 1, 255);
    float w2 = p2 - (float)lo2;
    float o2 = y2[(size_t)lo2 * DIN + d] * (1.0f - w2) + y2[(size_t)hi2 * DIN + d] * w2;

    float s0 = sw[0], s1 = sw[1], s2 = sw[2];
    float m = fmaxf(s0, fmaxf(s1, s2));
    float e0 = expf(s0 - m), e1 = expf(s1 - m), e2 = expf(s2 - m);
    float inv = 1.0f / (e0 + e1 + e2);

    fused[idx] = e0 * inv * o0 + e1 * inv * o1 + e2 * inv * o2;
    ctx[idx]   = (o0 + o1 + o2) * (1.0f / 3.0f);
}

// ---------------- pre ----------------
__global__ void pre_kernel(const float* __restrict__ fused, const float* __restrict__ gc,
                           const float* __restrict__ xz, float* __restrict__ pre)
{
    int idx = blockIdx.x * blockDim.x + threadIdx.x;
    int t = idx >> 11, d = idx & 2047;
    float gv = xz[(size_t)t * 4096 + 2048 + d];
    pre[idx] = fused[idx] * gc[idx] * siluf_(gv);
}

// ---------------- layernorm ----------------
__global__ __launch_bounds__(256)
void ln_kernel(const float* __restrict__ y, const float* __restrict__ g,
               const float* __restrict__ b, float* __restrict__ out)
{
    int t = blockIdx.x;
    const float* yr = y + (size_t)t * DIMP;
    float vals[4];
    float s = 0.0f, s2 = 0.0f;
#pragma unroll
    for (int i = 0; i < 4; i++) {
        float v = yr[threadIdx.x + i * 256];
        vals[i] = v; s += v; s2 += v * v;
    }
#pragma unroll
    for (int o = 16; o > 0; o >>= 1) {
        s  += __shfl_xor_sync(0xffffffffu, s, o);
        s2 += __shfl_xor_sync(0xffffffffu, s2, o);
    }
    __shared__ float rs[8], rs2[8];
    int warp = threadIdx.x >> 5, lane = threadIdx.x & 31;
    if (lane == 0) { rs[warp] = s; rs2[warp] = s2; }
    __syncthreads();
    if (threadIdx.x == 0) {
        float S = 0, S2 = 0;
#pragma unroll
        for (int i = 0; i < 8; i++) { S += rs[i]; S2 += rs2[i]; }
        rs[0] = S; rs2[0] = S2;
    }
    __syncthreads();
    float mu  = rs[0] * (1.0f / 1024.0f);
    float var = rs2[0] * (1.0f / 1024.0f) - mu * mu;
    float rstd = rsqrtf(var + 1e-5f);
#pragma unroll
    for (int i = 0; i < 4; i++) {
        int j = threadIdx.x + i * 256;
        out[(size_t)t * DIMP + j] = (vals[i] - mu) * rstd * g[j] + b[j];
    }
}

// ---------------- launch ------------------------------------------------------
extern "C" void kernel_launch(void* const* d_in, const int* in_sizes, int n_in,
                              void* d_out, int out_size)
{
    const float* x          = (const float*)d_in[0];
    const float* in_proj_w  = (const float*)d_in[1];
    const float* conv_w     = (const float*)d_in[2];
    const float* conv_b     = (const float*)d_in[3];
    const float* xproj_w    = (const float*)d_in[4];
    const float* dtproj_w   = (const float*)d_in[5];
    const float* dtproj_b   = (const float*)d_in[6];
    const float* D_param    = (const float*)d_in[7];
    const float* scale_w    = (const float*)d_in[8];
    const float* gate_w1    = (const float*)d_in[9];
    const float* gate_w2    = (const float*)d_in[10];
    const float* out_proj_w = (const float*)d_in[11];
    const float* ln_g       = (const float*)d_in[12];
    const float* ln_b       = (const float*)d_in[13];
    float* out = (float*)d_out;

    float *xz, *x1, *x2, *xc, *proj, *dt, *yb, *fused, *ctx, *g1, *gc, *pre, *yres;
    cudaGetSymbolAddress((void**)&xz,   g_xz);
    cudaGetSymbolAddress((void**)&x1,   g_x1);
    cudaGetSymbolAddress((void**)&x2,   g_x2);
    cudaGetSymbolAddress((void**)&xc,   g_xc);
    cudaGetSymbolAddress((void**)&proj, g_proj);
    cudaGetSymbolAddress((void**)&dt,   g_dt);
    cudaGetSymbolAddress((void**)&yb,   g_y);
    cudaGetSymbolAddress((void**)&fused,g_fused);
    cudaGetSymbolAddress((void**)&ctx,  g_ctx);
    cudaGetSymbolAddress((void**)&g1,   g_g1);
    cudaGetSymbolAddress((void**)&gc,   g_gc);
    cudaGetSymbolAddress((void**)&pre,  g_pre);
    cudaGetSymbolAddress((void**)&yres, g_yres);

    // 1) xz = x @ in_proj_w^T   [1024,4096]
    gemm_mma<0><<<dim3(4096 / 128, 1024 / 128), 256>>>(x, in_proj_w, xz, nullptr, 1024, 4096, 1024);

    // 2) downsample x_in
    down2_kernel<<<(512 * DIN) / 256, 256>>>(xz, x1);
    down4_kernel<<<(256 * DIN) / 256, 256>>>(xz, x2);

    // 3) per-scale SSM pipeline
    const int   Ts[3]     = {1024, 512, 256};
    const int   toff[3]   = {0, 1024, 1536};
    const int   xstr[3]   = {4096, DIN, DIN};
    const float* xs[3]; xs[0] = xz; xs[1] = x1; xs[2] = x2;

    for (int s = 0; s < 3; s++) {
        float* xc_s   = xc   + (size_t)toff[s] * DIN;
        float* proj_s = proj + (size_t)toff[s] * 32;
        float* dt_s   = dt   + (size_t)toff[s] * DIN;
        float* y_s    = yb   + (size_t)toff[s] * DIN;

        conv_silu_kernel<<<(Ts[s] * DIN) / 256, 256>>>(
            xs[s], xstr[s], conv_w + (size_t)s * DIN * 4, conv_b + (size_t)s * DIN, xc_s, Ts[s]);
        xproj_kernel<<<Ts[s], 256>>>(xc_s, xproj_w + (size_t)s * 32 * DIN, proj_s);
        dt_kernel<<<Ts[s] * 8, 256>>>(proj_s, dtproj_w + (size_t)s * DIN * 16,
                                      dtproj_b + (size_t)s * DIN, dt_s);
        scan_kernel<<<(DIN * NSTATE) / 256, 256>>>(dt_s, xc_s, proj_s,
                                                   D_param + (size_t)s * DIN, y_s, Ts[s]);
    }

    // 4) upsample + fuse + ctx
    fuse_kernel<<<(TLEN * DIN) / 256, 256>>>(yb, yb + (size_t)1024 * DIN, yb + (size_t)1536 * DIN,
                                             scale_w, fused, ctx);

    // 5) gating network
    gemm_mma<1><<<dim3(1024 / 128, 1024 / 128), 256>>>(ctx, gate_w1, g1, nullptr, 1024, 1024, 2048);
    gemm_mma<2><<<dim3(2048 / 128, 1024 / 128), 256>>>(g1, gate_w2, gc, nullptr, 1024, 2048, 1024);

    // 6) pre = fused * gate_ctx * silu(gate)
    pre_kernel<<<(TLEN * DIN) / 256, 256>>>(fused, gc, xz, pre);

    // 7) out_proj + residual
    gemm_mma<3><<<dim3(1024 / 128, 1024 / 128), 256>>>(pre, out_proj_w, yres, x, 1024, 1024, 2048);

    // 8) layernorm -> output
    ln_kernel<<<1024, 256>>>(yres, ln_g, ln_b, out);
}

// round 5
// speedup vs baseline: 1.9598x; 1.2056x over previous
#include <cuda_runtime.h>
#include <cuda_bf16.h>
#include <math.h>
#include <stdint.h>

// ---------------- problem constants ----------------
#define TLEN 1024
#define DIMP 1024
#define DIN  2048            // D_INNER
#define NSTATE 16
#define TSUM (1024+512+256)  // 1792

// ---------------- fp32 scratch ----------------
__device__ __align__(128) float g_xz   [TLEN*4096];
__device__ __align__(128) float g_x1   [512*DIN];
__device__ __align__(128) float g_x2   [256*DIN];
__device__ __align__(128) float g_xc   [TSUM*DIN];
__device__ __align__(128) float g_proj [TSUM*32];
__device__ __align__(128) float g_dt   [TSUM*DIN];
__device__ __align__(128) float g_y    [TSUM*DIN];
__device__ __align__(128) float g_fused[TLEN*DIN];
__device__ __align__(128) float g_gc   [TLEN*DIN];
__device__ __align__(128) float g_yres [TLEN*DIMP];

// ---------------- bf16 hi/lo operand scratch ----------------
__device__ __align__(128) __nv_bfloat16 g_xh  [TLEN*DIMP],  g_xl  [TLEN*DIMP];
__device__ __align__(128) __nv_bfloat16 g_w0h [4096*DIMP],  g_w0l [4096*DIMP];
__device__ __align__(128) __nv_bfloat16 g_ctxh[TLEN*DIN],   g_ctxl[TLEN*DIN];
__device__ __align__(128) __nv_bfloat16 g_w1h [DIMP*DIN],   g_w1l [DIMP*DIN];
__device__ __align__(128) __nv_bfloat16 g_g1h [TLEN*DIMP],  g_g1l [TLEN*DIMP];
__device__ __align__(128) __nv_bfloat16 g_w2h [DIN*DIMP],   g_w2l [DIN*DIMP];
__device__ __align__(128) __nv_bfloat16 g_preh[TLEN*DIN],   g_prel[TLEN*DIN];
__device__ __align__(128) __nv_bfloat16 g_w3h [DIMP*DIN],   g_w3l [DIMP*DIN];

// ---------------- helpers ----------------
__device__ __forceinline__ float sigmoidf_(float x) { return 1.0f / (1.0f + expf(-x)); }
__device__ __forceinline__ float siluf_(float x)    { return x / (1.0f + expf(-x)); }
__device__ __forceinline__ float softplusf_(float x) {
    return fmaxf(x, 0.0f) + log1pf(expf(-fabsf(x)));
}
__device__ __forceinline__ uint32_t smem_u32(const void* p) {
    uint32_t a;
    asm("{ .reg .u64 t; cvta.to.shared.u64 t, %1; cvt.u32.u64 %0, t; }" : "=r"(a) : "l"(p));
    return a;
}
__device__ __forceinline__ void cp16(uint32_t dst, const void* src) {
    asm volatile("cp.async.cg.shared.global [%0], [%1], 16;" :: "r"(dst), "l"(src));
}

// pack 4 floats into hi/lo bf16x2 pairs
__device__ __forceinline__ void split4(float4 v, uint2& hv, uint2& lv)
{
    __nv_bfloat162 h01 = __floats2bfloat162_rn(v.x, v.y);
    __nv_bfloat162 h23 = __floats2bfloat162_rn(v.z, v.w);
    float2 f01 = __bfloat1622float2(h01);
    float2 f23 = __bfloat1622float2(h23);
    __nv_bfloat162 l01 = __floats2bfloat162_rn(v.x - f01.x, v.y - f01.y);
    __nv_bfloat162 l23 = __floats2bfloat162_rn(v.z - f23.x, v.w - f23.y);
    hv.x = *(uint32_t*)&h01; hv.y = *(uint32_t*)&h23;
    lv.x = *(uint32_t*)&l01; lv.y = *(uint32_t*)&l23;
}

// ---------------- fp32 -> hi/lo bf16 conversion ----------------
__global__ void cvt_hilo_kernel(const float* __restrict__ in,
                                __nv_bfloat16* __restrict__ hi,
                                __nv_bfloat16* __restrict__ lo)
{
    int i = blockIdx.x * blockDim.x + threadIdx.x;   // per float4
    float4 v = ((const float4*)in)[i];
    uint2 hv, lv;
    split4(v, hv, lv);
    ((uint2*)hi)[i] = hv;
    ((uint2*)lo)[i] = lv;
}

// ============ tensor-core GEMM via mma.sync, preconverted bf16 hi/lo =========
// C[M,N] = A[M,K] @ B[N,K]^T ~= Ah*Bh + Ah*Bl + Al*Bh  (fp32 accum)
// BM_T x 128 CTA tile, BK=32, cp.async double buffer, 8 warps (2x4).
// EPI: 0 none(C fp32), 1 silu->Chi/Clo bf16, 2 sigmoid(C fp32), 3 C=acc+Res

#define MMA_BF16(c, a, b) \
  asm volatile("mma.sync.aligned.m16n8k16.row.col.f32.bf16.bf16.f32 " \
      "{%0,%1,%2,%3}, {%4,%5,%6,%7}, {%8,%9}, {%0,%1,%2,%3};" \
      : "+f"((c)[0]), "+f"((c)[1]), "+f"((c)[2]), "+f"((c)[3]) \
      : "r"((a)[0]), "r"((a)[1]), "r"((a)[2]), "r"((a)[3]), \
        "r"((b)[0]), "r"((b)[1]))

#define GPAD 40   // bf16 elems per smem row (32 data + 8 pad)

template<int EPI, int BM_T>
__global__ __launch_bounds__(256, 2)
void gemm_mma(const __nv_bfloat16* __restrict__ Ahi, const __nv_bfloat16* __restrict__ Alo,
              const __nv_bfloat16* __restrict__ Bhi, const __nv_bfloat16* __restrict__ Blo,
              float* __restrict__ C,
              __nv_bfloat16* __restrict__ Chi, __nv_bfloat16* __restrict__ Clo,
              const float* __restrict__ Res,
              int M, int N, int K)
{
    constexpr int A_EL  = BM_T * GPAD;
    constexpr int B_EL  = 128 * GPAD;
    constexpr int STAGE = 2 * A_EL + 2 * B_EL;   // elems per stage
    constexpr int MI    = BM_T / 32;             // m16 tiles per warp (4 or 2)

    extern __shared__ __nv_bfloat16 dyn[];
    const uint32_t dynb = smem_u32(dyn);

    const int tid  = threadIdx.x;
    const int warp = tid >> 5;
    const int lane = tid & 31;
    const int g    = lane >> 2;
    const int tig  = lane & 3;
    const int wm   = (warp >> 2) * (BM_T / 2);
    const int wn   = (warp & 3) * 32;
    const int bm   = blockIdx.y * BM_T;
    const int bn   = blockIdx.x * 128;

    float acc[MI][4][4];
#pragma unroll
    for (int mi = 0; mi < MI; mi++)
#pragma unroll
        for (int ni = 0; ni < 4; ni++)
#pragma unroll
            for (int q = 0; q < 4; q++) acc[mi][ni][q] = 0.0f;

    const int NC = K >> 5;

    auto issue = [&](int stg, int k0) {
        const uint32_t sb = dynb + stg * STAGE * 2;
#pragma unroll
        for (int i = 0; i < BM_T / 64; i++) {                 // A: BM_T*4/256 chunks/thread
            int c = tid + i * 256;
            int row = c >> 2, cc = (c & 3) << 3;
            uint32_t d = sb + (uint32_t)(row * GPAD + cc) * 2;
            size_t so = (size_t)(bm + row) * K + k0 + cc;
            cp16(d,              Ahi + so);
            cp16(d + A_EL * 2,   Alo + so);
        }
#pragma unroll
        for (int i = 0; i < 2; i++) {                         // B: 128 rows
            int c = tid + i * 256;
            int row = c >> 2, cc = (c & 3) << 3;
            uint32_t d = sb + (uint32_t)(2 * A_EL + row * GPAD + cc) * 2;
            size_t so = (size_t)(bn + row) * K + k0 + cc;
            cp16(d,              Bhi + so);
            cp16(d + B_EL * 2,   Blo + so);
        }
        asm volatile("cp.async.commit_group;" ::: "memory");
    };

    issue(0, 0);

    for (int c = 0; c < NC; c++) {
        if (c + 1 < NC) {
            issue((c + 1) & 1, (c + 1) << 5);
            asm volatile("cp.async.wait_group 1;" ::: "memory");
        } else {
            asm volatile("cp.async.wait_group 0;" ::: "memory");
        }
        __syncthreads();

        const __nv_bfloat16* sAh = dyn + (c & 1) * STAGE;
        const __nv_bfloat16* sAl = sAh + A_EL;
        const __nv_bfloat16* sBh = sAl + A_EL;
        const __nv_bfloat16* sBl = sBh + B_EL;

#pragma unroll
        for (int ks = 0; ks < 32; ks += 16) {
            const int ak = ks + tig * 2;
            uint32_t ahi[MI][4], bhi[4][2];
#pragma unroll
            for (int mi = 0; mi < MI; mi++) {
                int r0 = wm + mi * 16 + g;
                ahi[mi][0] = *(const uint32_t*)&sAh[(r0    ) * GPAD + ak];
                ahi[mi][1] = *(const uint32_t*)&sAh[(r0 + 8) * GPAD + ak];
                ahi[mi][2] = *(const uint32_t*)&sAh[(r0    ) * GPAD + ak + 8];
                ahi[mi][3] = *(const uint32_t*)&sAh[(r0 + 8) * GPAD + ak + 8];
            }
#pragma unroll
            for (int ni = 0; ni < 4; ni++) {
                int c0 = wn + ni * 8 + g;
                bhi[ni][0] = *(const uint32_t*)&sBh[c0 * GPAD + ak];
                bhi[ni][1] = *(const uint32_t*)&sBh[c0 * GPAD + ak + 8];
            }
#pragma unroll
            for (int mi = 0; mi < MI; mi++)
#pragma unroll
                for (int ni = 0; ni < 4; ni++)
                    MMA_BF16(acc[mi][ni], ahi[mi], bhi[ni]);
            {
                uint32_t blo[4][2];
#pragma unroll
                for (int ni = 0; ni < 4; ni++) {
                    int c0 = wn + ni * 8 + g;
                    blo[ni][0] = *(const uint32_t*)&sBl[c0 * GPAD + ak];
                    blo[ni][1] = *(const uint32_t*)&sBl[c0 * GPAD + ak + 8];
                }
#pragma unroll
                for (int mi = 0; mi < MI; mi++)
#pragma unroll
                    for (int ni = 0; ni < 4; ni++)
                        MMA_BF16(acc[mi][ni], ahi[mi], blo[ni]);
            }
            {
                uint32_t alo[MI][4];
#pragma unroll
                for (int mi = 0; mi < MI; mi++) {
                    int r0 = wm + mi * 16 + g;
                    alo[mi][0] = *(const uint32_t*)&sAl[(r0    ) * GPAD + ak];
                    alo[mi][1] = *(const uint32_t*)&sAl[(r0 + 8) * GPAD + ak];
                    alo[mi][2] = *(const uint32_t*)&sAl[(r0    ) * GPAD + ak + 8];
                    alo[mi][3] = *(const uint32_t*)&sAl[(r0 + 8) * GPAD + ak + 8];
                }
#pragma unroll
                for (int mi = 0; mi < MI; mi++)
#pragma unroll
                    for (int ni = 0; ni < 4; ni++)
                        MMA_BF16(acc[mi][ni], alo[mi], bhi[ni]);
            }
        }
        __syncthreads();
    }

    // ---- epilogue ----
#pragma unroll
    for (int mi = 0; mi < MI; mi++) {
        int row = bm + wm + mi * 16 + g;
#pragma unroll
        for (int ni = 0; ni < 4; ni++) {
            int col = bn + wn + ni * 8 + tig * 2;
            float v0 = acc[mi][ni][0], v1 = acc[mi][ni][1];
            float v2 = acc[mi][ni][2], v3 = acc[mi][ni][3];
            if (EPI == 1) {
                v0 = siluf_(v0); v1 = siluf_(v1); v2 = siluf_(v2); v3 = siluf_(v3);
                __nv_bfloat162 h01 = __floats2bfloat162_rn(v0, v1);
                __nv_bfloat162 h23 = __floats2bfloat162_rn(v2, v3);
                float2 f01 = __bfloat1622float2(h01);
                float2 f23 = __bfloat1622float2(h23);
                __nv_bfloat162 l01 = __floats2bfloat162_rn(v0 - f01.x, v1 - f01.y);
                __nv_bfloat162 l23 = __floats2bfloat162_rn(v2 - f23.x, v3 - f23.y);
                *(__nv_bfloat162*)(Chi + (size_t)row * N + col)       = h01;
                *(__nv_bfloat162*)(Chi + (size_t)(row + 8) * N + col) = h23;
                *(__nv_bfloat162*)(Clo + (size_t)row * N + col)       = l01;
                *(__nv_bfloat162*)(Clo + (size_t)(row + 8) * N + col) = l23;
            } else {
                if (EPI == 2) { v0 = sigmoidf_(v0); v1 = sigmoidf_(v1); v2 = sigmoidf_(v2); v3 = sigmoidf_(v3); }
                else if (EPI == 3) {
                    const float2 r0v = *(const float2*)(Res + (size_t)row * N + col);
                    const float2 r1v = *(const float2*)(Res + (size_t)(row + 8) * N + col);
                    v0 += r0v.x; v1 += r0v.y; v2 += r1v.x; v3 += r1v.y;
                }
                float2 o0; o0.x = v0; o0.y = v1;
                float2 o1; o1.x = v2; o1.y = v3;
                *(float2*)(C + (size_t)row * N + col)       = o0;
                *(float2*)(C + (size_t)(row + 8) * N + col) = o1;
            }
        }
    }
}

// ---------------- downsample ----------------
__global__ void down2_kernel(const float* __restrict__ xz, float* __restrict__ o)
{
    int idx = blockIdx.x * blockDim.x + threadIdx.x;
    int t = idx >> 11, d = idx & 2047;
    o[idx] = 0.5f * (xz[(size_t)(2 * t) * 4096 + d] + xz[(size_t)(2 * t + 1) * 4096 + d]);
}
__global__ void down4_kernel(const float* __restrict__ xz, float* __restrict__ o)
{
    int idx = blockIdx.x * blockDim.x + threadIdx.x;
    int t = idx >> 11, d = idx & 2047;
    float s = xz[(size_t)(4 * t) * 4096 + d] + xz[(size_t)(4 * t + 1) * 4096 + d]
            + xz[(size_t)(4 * t + 2) * 4096 + d] + xz[(size_t)(4 * t + 3) * 4096 + d];
    o[idx] = 0.25f * s;
}

// ---------------- causal depthwise conv (K=4) + silu ----------------
__global__ void conv_silu_kernel(const float* __restrict__ x, int xs,
                                 const float* __restrict__ w, const float* __restrict__ b,
                                 float* __restrict__ xc, int T)
{
    int idx = blockIdx.x * blockDim.x + threadIdx.x;
    int t = idx >> 11, d = idx & 2047;
    float4 wv = *(const float4*)(w + d * 4);
    float acc = b[d];
    if (t >= 3) acc = fmaf(x[(size_t)(t - 3) * xs + d], wv.x, acc);
    if (t >= 2) acc = fmaf(x[(size_t)(t - 2) * xs + d], wv.y, acc);
    if (t >= 1) acc = fmaf(x[(size_t)(t - 1) * xs + d], wv.z, acc);
    acc = fmaf(x[(size_t)t * xs + d], wv.w, acc);
    xc[(size_t)t * DIN + d] = acc * sigmoidf_(acc);
}

// ---------------- xproj ----------------
__global__ __launch_bounds__(256)
void xproj_kernel(const float* __restrict__ xc, const float* __restrict__ xw,
                  float* __restrict__ proj)
{
    int t = blockIdx.x;
    int warp = threadIdx.x >> 5, lane = threadIdx.x & 31;
    const float* xr = xc + (size_t)t * DIN;
    float acc0 = 0, acc1 = 0, acc2 = 0, acc3 = 0;
    const float* w0 = xw + (size_t)(warp * 4 + 0) * DIN;
    const float* w1 = xw + (size_t)(warp * 4 + 1) * DIN;
    const float* w2 = xw + (size_t)(warp * 4 + 2) * DIN;
    const float* w3 = xw + (size_t)(warp * 4 + 3) * DIN;
    for (int k = lane; k < DIN; k += 32) {
        float xv = xr[k];
        acc0 = fmaf(xv, w0[k], acc0);
        acc1 = fmaf(xv, w1[k], acc1);
        acc2 = fmaf(xv, w2[k], acc2);
        acc3 = fmaf(xv, w3[k], acc3);
    }
#pragma unroll
    for (int o = 16; o > 0; o >>= 1) {
        acc0 += __shfl_xor_sync(0xffffffffu, acc0, o);
        acc1 += __shfl_xor_sync(0xffffffffu, acc1, o);
        acc2 += __shfl_xor_sync(0xffffffffu, acc2, o);
        acc3 += __shfl_xor_sync(0xffffffffu, acc3, o);
    }
    if (lane == 0) {
        proj[t * 32 + warp * 4 + 0] = acc0;
        proj[t * 32 + warp * 4 + 1] = acc1;
        proj[t * 32 + warp * 4 + 2] = acc2;
        proj[t * 32 + warp * 4 + 3] = acc3;
    }
}

// ---------------- dt ----------------
__global__ void dt_kernel(const float* __restrict__ proj, const float* __restrict__ dtw,
                          const float* __restrict__ dtb, float* __restrict__ dt)
{
    int t  = blockIdx.x >> 3;
    int d  = ((blockIdx.x & 7) << 8) + threadIdx.x;
    __shared__ float Bs[16];
    if (threadIdx.x < 16) Bs[threadIdx.x] = proj[t * 32 + threadIdx.x];
    __syncthreads();
    const float4* wp = (const float4*)(dtw + (size_t)d * 16);
    float4 w0 = wp[0], w1 = wp[1], w2 = wp[2], w3 = wp[3];
    float acc = dtb[d];
    acc = fmaf(Bs[0],  w0.x, acc); acc = fmaf(Bs[1],  w0.y, acc);
    acc = fmaf(Bs[2],  w0.z, acc); acc = fmaf(Bs[3],  w0.w, acc);
    acc = fmaf(Bs[4],  w1.x, acc); acc = fmaf(Bs[5],  w1.y, acc);
    acc = fmaf(Bs[6],  w1.z, acc); acc = fmaf(Bs[7],  w1.w, acc);
    acc = fmaf(Bs[8],  w2.x, acc); acc = fmaf(Bs[9],  w2.y, acc);
    acc = fmaf(Bs[10], w2.z, acc); acc = fmaf(Bs[11], w2.w, acc);
    acc = fmaf(Bs[12], w3.x, acc); acc = fmaf(Bs[13], w3.y, acc);
    acc = fmaf(Bs[14], w3.z, acc); acc = fmaf(Bs[15], w3.w, acc);
    dt[(size_t)t * DIN + d] = softplusf_(softplusf_(acc));
}

// ---------------- selective scan ----------------
__global__ __launch_bounds__(256)
void scan_kernel(const float* __restrict__ dt, const float* __restrict__ xc,
                 const float* __restrict__ proj, const float* __restrict__ Dp,
                 float* __restrict__ y, int T)
{
    int gid = blockIdx.x * blockDim.x + threadIdx.x;
    int d = gid >> 4;
    int s = gid & 15;
    const float A = -(float)(s + 1);
    const float Dd = Dp[d];
    float h = 0.0f;
    for (int t = 0; t < T; t++) {
        float dtv = dt[(size_t)t * DIN + d];
        float xcv = xc[(size_t)t * DIN + d];
        float Bv  = proj[t * 32 + s];
        float Cv  = proj[t * 32 + 16 + s];
        float da  = fmaxf(expf(dtv * A), 1e-38f);
        float dbx = fmaxf(dtv * Bv * xcv, 1e-38f);
        h = fmaf(da, h, dbx);
        float v = Cv * h;
        v += __shfl_xor_sync(0xffffffffu, v, 8, 16);
        v += __shfl_xor_sync(0xffffffffu, v, 4, 16);
        v += __shfl_xor_sync(0xffffffffu, v, 2, 16);
        v += __shfl_xor_sync(0xffffffffu, v, 1, 16);
        if (s == 0) y[(size_t)t * DIN + d] = v + Dd * xcv;
    }
}

// ---------------- fuse: fused fp32 + ctx hi/lo bf16 ----------------
__global__ void fuse_kernel(const float* __restrict__ y0, const float* __restrict__ y1,
                            const float* __restrict__ y2, const float* __restrict__ sw,
                            float* __restrict__ fused,
                            __nv_bfloat16* __restrict__ ctxh, __nv_bfloat16* __restrict__ ctxl)
{
    int idx = blockIdx.x * blockDim.x + threadIdx.x;
    int t = idx >> 11, d = idx & 2047;

    float o0 = y0[idx];

    float p1 = fminf(fmaxf(0.5f * (float)t - 0.25f, 0.0f), 511.0f);
    int lo1 = (int)floorf(p1);
    int hi1 = min(lo1 + 1, 511);
    float w1 = p1 - (float)lo1;
    float o1 = y1[(size_t)lo1 * DIN + d] * (1.0f - w1) + y1[(size_t)hi1 * DIN + d] * w1;

    float p2 = fminf(fmaxf(0.25f * (float)t - 0.375f, 0.0f), 255.0f);
    int lo2 = (int)floorf(p2);
    int hi2 = min(lo2 + 1, 255);
    float w2 = p2 - (float)lo2;
    float o2 = y2[(size_t)lo2 * DIN + d] * (1.0f - w2) + y2[(size_t)hi2 * DIN + d] * w2;

    float s0 = sw[0], s1 = sw[1], s2 = sw[2];
    float m = fmaxf(s0, fmaxf(s1, s2));
    float e0 = expf(s0 - m), e1 = expf(s1 - m), e2 = expf(s2 - m);
    float inv = 1.0f / (e0 + e1 + e2);

    fused[idx] = e0 * inv * o0 + e1 * inv * o1 + e2 * inv * o2;
    float cv = (o0 + o1 + o2) * (1.0f / 3.0f);
    __nv_bfloat16 h = __float2bfloat16_rn(cv);
    ctxh[idx] = h;
    ctxl[idx] = __float2bfloat16_rn(cv - __bfloat162float(h));
}

// ---------------- pre = fused * gate_ctx * silu(gate) -> hi/lo bf16 -----------
__global__ void pre_kernel(const float* __restrict__ fused, const float* __restrict__ gc,
                           const float* __restrict__ xz,
                           __nv_bfloat16* __restrict__ preh, __nv_bfloat16* __restrict__ prel)
{
    int idx = blockIdx.x * blockDim.x + threadIdx.x;
    int t = idx >> 11, d = idx & 2047;
    float gv = xz[(size_t)t * 4096 + 2048 + d];
    float v = fused[idx] * gc[idx] * siluf_(gv);
    __nv_bfloat16 h = __float2bfloat16_rn(v);
    preh[idx] = h;
    prel[idx] = __float2bfloat16_rn(v - __bfloat162float(h));
}

// ---------------- layernorm ----------------
__global__ __launch_bounds__(256)
void ln_kernel(const float* __restrict__ y, const float* __restrict__ g,
               const float* __restrict__ b, float* __restrict__ out)
{
    int t = blockIdx.x;
    const float* yr = y + (size_t)t * DIMP;
    float vals[4];
    float s = 0.0f, s2 = 0.0f;
#pragma unroll
    for (int i = 0; i < 4; i++) {
        float v = yr[threadIdx.x + i * 256];
        vals[i] = v; s += v; s2 += v * v;
    }
#pragma unroll
    for (int o = 16; o > 0; o >>= 1) {
        s  += __shfl_xor_sync(0xffffffffu, s, o);
        s2 += __shfl_xor_sync(0xffffffffu, s2, o);
    }
    __shared__ float rs[8], rs2[8];
    int warp = threadIdx.x >> 5, lane = threadIdx.x & 31;
    if (lane == 0) { rs[warp] = s; rs2[warp] = s2; }
    __syncthreads();
    if (threadIdx.x == 0) {
        float S = 0, S2 = 0;
#pragma unroll
        for (int i = 0; i < 8; i++) { S += rs[i]; S2 += rs2[i]; }
        rs[0] = S; rs2[0] = S2;
    }
    __syncthreads();
    float mu  = rs[0] * (1.0f / 1024.0f);
    float var = rs2[0] * (1.0f / 1024.0f) - mu * mu;
    float rstd = rsqrtf(var + 1e-5f);
#pragma unroll
    for (int i = 0; i < 4; i++) {
        int j = threadIdx.x + i * 256;
        out[(size_t)t * DIMP + j] = (vals[i] - mu) * rstd * g[j] + b[j];
    }
}

// ---------------- launch ------------------------------------------------------
extern "C" void kernel_launch(void* const* d_in, const int* in_sizes, int n_in,
                              void* d_out, int out_size)
{
    const float* x          = (const float*)d_in[0];
    const float* in_proj_w  = (const float*)d_in[1];
    const float* conv_w     = (const float*)d_in[2];
    const float* conv_b     = (const float*)d_in[3];
    const float* xproj_w    = (const float*)d_in[4];
    const float* dtproj_w   = (const float*)d_in[5];
    const float* dtproj_b   = (const float*)d_in[6];
    const float* D_param    = (const float*)d_in[7];
    const float* scale_w    = (const float*)d_in[8];
    const float* gate_w1    = (const float*)d_in[9];
    const float* gate_w2    = (const float*)d_in[10];
    const float* out_proj_w = (const float*)d_in[11];
    const float* ln_g       = (const float*)d_in[12];
    const float* ln_b       = (const float*)d_in[13];
    float* out = (float*)d_out;

    float *xz, *x1, *x2, *xc, *proj, *dt, *yb, *fused, *gc, *yres;
    cudaGetSymbolAddress((void**)&xz,   g_xz);
    cudaGetSymbolAddress((void**)&x1,   g_x1);
    cudaGetSymbolAddress((void**)&x2,   g_x2);
    cudaGetSymbolAddress((void**)&xc,   g_xc);
    cudaGetSymbolAddress((void**)&proj, g_proj);
    cudaGetSymbolAddress((void**)&dt,   g_dt);
    cudaGetSymbolAddress((void**)&yb,   g_y);
    cudaGetSymbolAddress((void**)&fused,g_fused);
    cudaGetSymbolAddress((void**)&gc,   g_gc);
    cudaGetSymbolAddress((void**)&yres, g_yres);

    __nv_bfloat16 *xh,*xl,*w0h,*w0l,*ctxh,*ctxl,*w1h,*w1l,*g1h,*g1l,*w2h,*w2l,*preh,*prel,*w3h,*w3l;
    cudaGetSymbolAddress((void**)&xh,  g_xh);   cudaGetSymbolAddress((void**)&xl,  g_xl);
    cudaGetSymbolAddress((void**)&w0h, g_w0h);  cudaGetSymbolAddress((void**)&w0l, g_w0l);
    cudaGetSymbolAddress((void**)&ctxh,g_ctxh); cudaGetSymbolAddress((void**)&ctxl,g_ctxl);
    cudaGetSymbolAddress((void**)&w1h, g_w1h);  cudaGetSymbolAddress((void**)&w1l, g_w1l);
    cudaGetSymbolAddress((void**)&g1h, g_g1h);  cudaGetSymbolAddress((void**)&g1l, g_g1l);
    cudaGetSymbolAddress((void**)&w2h, g_w2h);  cudaGetSymbolAddress((void**)&w2l, g_w2l);
    cudaGetSymbolAddress((void**)&preh,g_preh); cudaGetSymbolAddress((void**)&prel,g_prel);
    cudaGetSymbolAddress((void**)&w3h, g_w3h);  cudaGetSymbolAddress((void**)&w3l, g_w3l);

    // dynamic smem opt-in (idempotent)
    constexpr int SM128 = (2 * (2 * 128 * GPAD + 2 * 128 * GPAD)) * 2;  // 81920 B
    constexpr int SM64  = (2 * (2 * 64  * GPAD + 2 * 128 * GPAD)) * 2;  // 61440 B
    cudaFuncSetAttribute(gemm_mma<0,128>, cudaFuncAttributeMaxDynamicSharedMemorySize, SM128);
    cudaFuncSetAttribute(gemm_mma<1,64>,  cudaFuncAttributeMaxDynamicSharedMemorySize, SM64);
    cudaFuncSetAttribute(gemm_mma<2,64>,  cudaFuncAttributeMaxDynamicSharedMemorySize, SM64);
    cudaFuncSetAttribute(gemm_mma<3,64>,  cudaFuncAttributeMaxDynamicSharedMemorySize, SM64);

    // 0) preconvert x + all weights to bf16 hi/lo
    cvt_hilo_kernel<<<(TLEN*DIMP/4)/256, 256>>>(x, xh, xl);
    cvt_hilo_kernel<<<(4096*DIMP/4)/256, 256>>>(in_proj_w, w0h, w0l);
    cvt_hilo_kernel<<<(DIMP*DIN/4)/256, 256>>>(gate_w1, w1h, w1l);
    cvt_hilo_kernel<<<(DIN*DIMP/4)/256, 256>>>(gate_w2, w2h, w2l);
    cvt_hilo_kernel<<<(DIMP*DIN/4)/256, 256>>>(out_proj_w, w3h, w3l);

    // 1) xz = x @ in_proj_w^T   [1024,4096]
    gemm_mma<0,128><<<dim3(32, 8), 256, SM128>>>(xh, xl, w0h, w0l, xz, nullptr, nullptr, nullptr,
                                                 1024, 4096, 1024);

    // 2) downsample
    down2_kernel<<<(512 * DIN) / 256, 256>>>(xz, x1);
    down4_kernel<<<(256 * DIN) / 256, 256>>>(xz, x2);

    // 3) per-scale SSM
    const int   Ts[3]   = {1024, 512, 256};
    const int   toff[3] = {0, 1024, 1536};
    const int   xstr[3] = {4096, DIN, DIN};
    const float* xs[3]; xs[0] = xz; xs[1] = x1; xs[2] = x2;

    for (int s = 0; s < 3; s++) {
        float* xc_s   = xc   + (size_t)toff[s] * DIN;
        float* proj_s = proj + (size_t)toff[s] * 32;
        float* dt_s   = dt   + (size_t)toff[s] * DIN;
        float* y_s    = yb   + (size_t)toff[s] * DIN;

        conv_silu_kernel<<<(Ts[s] * DIN) / 256, 256>>>(
            xs[s], xstr[s], conv_w + (size_t)s * DIN * 4, conv_b + (size_t)s * DIN, xc_s, Ts[s]);
        xproj_kernel<<<Ts[s], 256>>>(xc_s, xproj_w + (size_t)s * 32 * DIN, proj_s);
        dt_kernel<<<Ts[s] * 8, 256>>>(proj_s, dtproj_w + (size_t)s * DIN * 16,
                                      dtproj_b + (size_t)s * DIN, dt_s);
        scan_kernel<<<(DIN * NSTATE) / 256, 256>>>(dt_s, xc_s, proj_s,
                                                   D_param + (size_t)s * DIN, y_s, Ts[s]);
    }

    // 4) fuse -> fused fp32, ctx hi/lo
    fuse_kernel<<<(TLEN * DIN) / 256, 256>>>(yb, yb + (size_t)1024 * DIN, yb + (size_t)1536 * DIN,
                                             scale_w, fused, ctxh, ctxl);

    // 5) gating: g1 = silu(ctx @ gate_w1^T) (bf16 hi/lo out); gc = sigmoid(g1 @ gate_w2^T)
    gemm_mma<1,64><<<dim3(8, 16), 256, SM64>>>(ctxh, ctxl, w1h, w1l, nullptr, g1h, g1l, nullptr,
                                               1024, 1024, 2048);
    gemm_mma<2,64><<<dim3(16, 16), 256, SM64>>>(g1h, g1l, w2h, w2l, gc, nullptr, nullptr, nullptr,
                                                1024, 2048, 1024);

    // 6) pre (bf16 hi/lo out)
    pre_kernel<<<(TLEN * DIN) / 256, 256>>>(fused, gc, xz, preh, prel);

    // 7) out_proj + residual
    gemm_mma<3,64><<<dim3(8, 16), 256, SM64>>>(preh, prel, w3h, w3l, yres, nullptr, nullptr, x,
                                               1024, 1024, 2048);

    // 8) layernorm
    ln_kernel<<<1024, 256>>>(yres, ln_g, ln_b, out);
}

// round 6
// speedup vs baseline: 2.0332x; 1.0374x over previous
#include <cuda_runtime.h>
#include <cuda_bf16.h>
#include <math.h>
#include <stdint.h>

// ---------------- problem constants ----------------
#define TLEN 1024
#define DIMP 1024
#define DIN  2048            // D_INNER
#define NSTATE 16
#define TSUM (1024+512+256)  // 1792

// ---------------- fp32 scratch ----------------
__device__ __align__(128) float g_xz   [TLEN*4096];
__device__ __align__(128) float g_x1   [512*DIN];
__device__ __align__(128) float g_x2   [256*DIN];
__device__ __align__(128) float g_xc   [TSUM*DIN];
__device__ __align__(128) float g_proj [TSUM*32];
__device__ __align__(128) float g_dt   [TSUM*DIN];
__device__ __align__(128) float g_y    [TSUM*DIN];
__device__ __align__(128) float g_fused[TLEN*DIN];
__device__ __align__(128) float g_gc   [TLEN*DIN];
__device__ __align__(128) float g_yres [TLEN*DIMP];

// ---------------- bf16 hi/lo operand scratch ----------------
__device__ __align__(128) __nv_bfloat16 g_xh  [TLEN*DIMP],  g_xl  [TLEN*DIMP];
__device__ __align__(128) __nv_bfloat16 g_w0h [4096*DIMP],  g_w0l [4096*DIMP];
__device__ __align__(128) __nv_bfloat16 g_ctxh[TLEN*DIN],   g_ctxl[TLEN*DIN];
__device__ __align__(128) __nv_bfloat16 g_w1h [DIMP*DIN],   g_w1l [DIMP*DIN];
__device__ __align__(128) __nv_bfloat16 g_g1h [TLEN*DIMP],  g_g1l [TLEN*DIMP];
__device__ __align__(128) __nv_bfloat16 g_w2h [DIN*DIMP],   g_w2l [DIN*DIMP];
__device__ __align__(128) __nv_bfloat16 g_preh[TLEN*DIN],   g_prel[TLEN*DIN];
__device__ __align__(128) __nv_bfloat16 g_w3h [DIMP*DIN],   g_w3l [DIMP*DIN];

// ---------------- helpers ----------------
__device__ __forceinline__ float sigmoidf_(float x) { return 1.0f / (1.0f + expf(-x)); }
__device__ __forceinline__ float siluf_(float x)    { return x / (1.0f + expf(-x)); }
__device__ __forceinline__ float softplusf_(float x) {
    return fmaxf(x, 0.0f) + log1pf(expf(-fabsf(x)));
}
__device__ __forceinline__ uint32_t smem_u32(const void* p) {
    uint32_t a;
    asm("{ .reg .u64 t; cvta.to.shared.u64 t, %1; cvt.u32.u64 %0, t; }" : "=r"(a) : "l"(p));
    return a;
}
__device__ __forceinline__ void cp16(uint32_t dst, const void* src) {
    asm volatile("cp.async.cg.shared.global [%0], [%1], 16;" :: "r"(dst), "l"(src));
}

__device__ __forceinline__ void split4(float4 v, uint2& hv, uint2& lv)
{
    __nv_bfloat162 h01 = __floats2bfloat162_rn(v.x, v.y);
    __nv_bfloat162 h23 = __floats2bfloat162_rn(v.z, v.w);
    float2 f01 = __bfloat1622float2(h01);
    float2 f23 = __bfloat1622float2(h23);
    __nv_bfloat162 l01 = __floats2bfloat162_rn(v.x - f01.x, v.y - f01.y);
    __nv_bfloat162 l23 = __floats2bfloat162_rn(v.z - f23.x, v.w - f23.y);
    hv.x = *(uint32_t*)&h01; hv.y = *(uint32_t*)&h23;
    lv.x = *(uint32_t*)&l01; lv.y = *(uint32_t*)&l23;
}

__global__ void cvt_hilo_kernel(const float* __restrict__ in,
                                __nv_bfloat16* __restrict__ hi,
                                __nv_bfloat16* __restrict__ lo)
{
    int i = blockIdx.x * blockDim.x + threadIdx.x;
    float4 v = ((const float4*)in)[i];
    uint2 hv, lv;
    split4(v, hv, lv);
    ((uint2*)hi)[i] = hv;
    ((uint2*)lo)[i] = lv;
}

// ============ tensor-core GEMM via mma.sync + ldmatrix, bf16 hi/lo ===========
#define MMA_BF16(c, a, b) \
  asm volatile("mma.sync.aligned.m16n8k16.row.col.f32.bf16.bf16.f32 " \
      "{%0,%1,%2,%3}, {%4,%5,%6,%7}, {%8,%9}, {%0,%1,%2,%3};" \
      : "+f"((c)[0]), "+f"((c)[1]), "+f"((c)[2]), "+f"((c)[3]) \
      : "r"((a)[0]), "r"((a)[1]), "r"((a)[2]), "r"((a)[3]), \
        "r"((b)[0]), "r"((b)[1]))

#define LDSM_X4(r, addr) \
  asm volatile("ldmatrix.sync.aligned.m8n8.x4.shared.b16 {%0,%1,%2,%3}, [%4];" \
      : "=r"((r)[0]), "=r"((r)[1]), "=r"((r)[2]), "=r"((r)[3]) : "r"(addr))

#define GPAD 40   // bf16 elems per smem row (32 data + 8 pad); LDSM conflict-free

template<int EPI, int BM_T>
__global__ __launch_bounds__(256, 2)
void gemm_mma(const __nv_bfloat16* __restrict__ Ahi, const __nv_bfloat16* __restrict__ Alo,
              const __nv_bfloat16* __restrict__ Bhi, const __nv_bfloat16* __restrict__ Blo,
              float* __restrict__ C,
              __nv_bfloat16* __restrict__ Chi, __nv_bfloat16* __restrict__ Clo,
              const float* __restrict__ Res,
              int M, int N, int K)
{
    constexpr int A_EL  = BM_T * GPAD;
    constexpr int B_EL  = 128 * GPAD;
    constexpr int STAGE = 2 * A_EL + 2 * B_EL;
    constexpr int MI    = BM_T / 32;

    extern __shared__ __nv_bfloat16 dyn[];
    const uint32_t dynb = smem_u32(dyn);

    const int tid  = threadIdx.x;
    const int warp = tid >> 5;
    const int lane = tid & 31;
    const int g    = lane >> 2;
    const int tig  = lane & 3;
    const int wm   = (warp >> 2) * (BM_T / 2);
    const int wn   = (warp & 3) * 32;
    const int bm   = blockIdx.y * BM_T;
    const int bn   = blockIdx.x * 128;

    // ldmatrix per-lane offsets (elements)
    const int lh = lane & 15;
    const int kh = (lane >> 4) << 3;
    const uint32_t aoff = (uint32_t)((wm + lh) * GPAD + kh) * 2;
    const uint32_t boff = (uint32_t)((wn + lh) * GPAD + kh) * 2;

    float acc[MI][4][4];
#pragma unroll
    for (int mi = 0; mi < MI; mi++)
#pragma unroll
        for (int ni = 0; ni < 4; ni++)
#pragma unroll
            for (int q = 0; q < 4; q++) acc[mi][ni][q] = 0.0f;

    const int NC = K >> 5;

    auto issue = [&](int stg, int k0) {
        const uint32_t sb = dynb + stg * STAGE * 2;
#pragma unroll
        for (int i = 0; i < BM_T / 64; i++) {
            int c = tid + i * 256;
            int row = c >> 2, cc = (c & 3) << 3;
            uint32_t d = sb + (uint32_t)(row * GPAD + cc) * 2;
            size_t so = (size_t)(bm + row) * K + k0 + cc;
            cp16(d,            Ahi + so);
            cp16(d + A_EL * 2, Alo + so);
        }
#pragma unroll
        for (int i = 0; i < 2; i++) {
            int c = tid + i * 256;
            int row = c >> 2, cc = (c & 3) << 3;
            uint32_t d = sb + (uint32_t)(2 * A_EL + row * GPAD + cc) * 2;
            size_t so = (size_t)(bn + row) * K + k0 + cc;
            cp16(d,            Bhi + so);
            cp16(d + B_EL * 2, Blo + so);
        }
        asm volatile("cp.async.commit_group;" ::: "memory");
    };

    issue(0, 0);

    for (int c = 0; c < NC; c++) {
        if (c + 1 < NC) {
            issue((c + 1) & 1, (c + 1) << 5);
            asm volatile("cp.async.wait_group 1;" ::: "memory");
        } else {
            asm volatile("cp.async.wait_group 0;" ::: "memory");
        }
        __syncthreads();

        const uint32_t sb  = dynb + (c & 1) * STAGE * 2;
        const uint32_t aHi = sb;
        const uint32_t aLo = sb + A_EL * 2;
        const uint32_t bHi = sb + 2 * A_EL * 2;
        const uint32_t bLo = sb + (2 * A_EL + B_EL) * 2;

#pragma unroll
        for (int ks = 0; ks < 32; ks += 16) {
            const uint32_t ko = (uint32_t)ks * 2;
            uint32_t afr[MI][4], bfr[4][2];
            // A hi fragments
#pragma unroll
            for (int mi = 0; mi < MI; mi++)
                LDSM_X4(afr[mi], aHi + aoff + (uint32_t)(mi * 16 * GPAD) * 2 + ko);
            // B hi fragments (2 x4 loads cover 32 cols)
#pragma unroll
            for (int p = 0; p < 2; p++) {
                uint32_t r[4];
                LDSM_X4(r, bHi + boff + (uint32_t)(p * 16 * GPAD) * 2 + ko);
                bfr[2 * p][0] = r[0]; bfr[2 * p][1] = r[2];
                bfr[2 * p + 1][0] = r[1]; bfr[2 * p + 1][1] = r[3];
            }
            // pass 1: Ah * Bh
#pragma unroll
            for (int mi = 0; mi < MI; mi++)
#pragma unroll
                for (int ni = 0; ni < 4; ni++)
                    MMA_BF16(acc[mi][ni], afr[mi], bfr[ni]);
            // pass 2: Ah * Bl
            {
                uint32_t bl[4][2];
#pragma unroll
                for (int p = 0; p < 2; p++) {
                    uint32_t r[4];
                    LDSM_X4(r, bLo + boff + (uint32_t)(p * 16 * GPAD) * 2 + ko);
                    bl[2 * p][0] = r[0]; bl[2 * p][1] = r[2];
                    bl[2 * p + 1][0] = r[1]; bl[2 * p + 1][1] = r[3];
                }
#pragma unroll
                for (int mi = 0; mi < MI; mi++)
#pragma unroll
                    for (int ni = 0; ni < 4; ni++)
                        MMA_BF16(acc[mi][ni], afr[mi], bl[ni]);
            }
            // pass 3: Al * Bh (reuse afr storage)
#pragma unroll
            for (int mi = 0; mi < MI; mi++)
                LDSM_X4(afr[mi], aLo + aoff + (uint32_t)(mi * 16 * GPAD) * 2 + ko);
#pragma unroll
            for (int mi = 0; mi < MI; mi++)
#pragma unroll
                for (int ni = 0; ni < 4; ni++)
                    MMA_BF16(acc[mi][ni], afr[mi], bfr[ni]);
        }
        __syncthreads();
    }

    // ---- epilogue ----
#pragma unroll
    for (int mi = 0; mi < MI; mi++) {
        int row = bm + wm + mi * 16 + g;
#pragma unroll
        for (int ni = 0; ni < 4; ni++) {
            int col = bn + wn + ni * 8 + tig * 2;
            float v0 = acc[mi][ni][0], v1 = acc[mi][ni][1];
            float v2 = acc[mi][ni][2], v3 = acc[mi][ni][3];
            if (EPI == 1) {
                v0 = siluf_(v0); v1 = siluf_(v1); v2 = siluf_(v2); v3 = siluf_(v3);
                __nv_bfloat162 h01 = __floats2bfloat162_rn(v0, v1);
                __nv_bfloat162 h23 = __floats2bfloat162_rn(v2, v3);
                float2 f01 = __bfloat1622float2(h01);
                float2 f23 = __bfloat1622float2(h23);
                __nv_bfloat162 l01 = __floats2bfloat162_rn(v0 - f01.x, v1 - f01.y);
                __nv_bfloat162 l23 = __floats2bfloat162_rn(v2 - f23.x, v3 - f23.y);
                *(__nv_bfloat162*)(Chi + (size_t)row * N + col)       = h01;
                *(__nv_bfloat162*)(Chi + (size_t)(row + 8) * N + col) = h23;
                *(__nv_bfloat162*)(Clo + (size_t)row * N + col)       = l01;
                *(__nv_bfloat162*)(Clo + (size_t)(row + 8) * N + col) = l23;
            } else {
                if (EPI == 2) { v0 = sigmoidf_(v0); v1 = sigmoidf_(v1); v2 = sigmoidf_(v2); v3 = sigmoidf_(v3); }
                else if (EPI == 3) {
                    const float2 r0v = *(const float2*)(Res + (size_t)row * N + col);
                    const float2 r1v = *(const float2*)(Res + (size_t)(row + 8) * N + col);
                    v0 += r0v.x; v1 += r0v.y; v2 += r1v.x; v3 += r1v.y;
                }
                float2 o0; o0.x = v0; o0.y = v1;
                float2 o1; o1.x = v2; o1.y = v3;
                *(float2*)(C + (size_t)row * N + col)       = o0;
                *(float2*)(C + (size_t)(row + 8) * N + col) = o1;
            }
        }
    }
}

// ---------------- downsample ----------------
__global__ void down2_kernel(const float* __restrict__ xz, float* __restrict__ o)
{
    int idx = blockIdx.x * blockDim.x + threadIdx.x;
    int t = idx >> 11, d = idx & 2047;
    o[idx] = 0.5f * (xz[(size_t)(2 * t) * 4096 + d] + xz[(size_t)(2 * t + 1) * 4096 + d]);
}
__global__ void down4_kernel(const float* __restrict__ xz, float* __restrict__ o)
{
    int idx = blockIdx.x * blockDim.x + threadIdx.x;
    int t = idx >> 11, d = idx & 2047;
    float s = xz[(size_t)(4 * t) * 4096 + d] + xz[(size_t)(4 * t + 1) * 4096 + d]
            + xz[(size_t)(4 * t + 2) * 4096 + d] + xz[(size_t)(4 * t + 3) * 4096 + d];
    o[idx] = 0.25f * s;
}

// ---------------- causal depthwise conv (K=4) + silu ----------------
__global__ void conv_silu_kernel(const float* __restrict__ x, int xs,
                                 const float* __restrict__ w, const float* __restrict__ b,
                                 float* __restrict__ xc, int T)
{
    int idx = blockIdx.x * blockDim.x + threadIdx.x;
    int t = idx >> 11, d = idx & 2047;
    float4 wv = *(const float4*)(w + d * 4);
    float acc = b[d];
    if (t >= 3) acc = fmaf(x[(size_t)(t - 3) * xs + d], wv.x, acc);
    if (t >= 2) acc = fmaf(x[(size_t)(t - 2) * xs + d], wv.y, acc);
    if (t >= 1) acc = fmaf(x[(size_t)(t - 1) * xs + d], wv.z, acc);
    acc = fmaf(x[(size_t)t * xs + d], wv.w, acc);
    xc[(size_t)t * DIN + d] = acc * sigmoidf_(acc);
}

// ---------------- xproj ----------------
__global__ __launch_bounds__(256)
void xproj_kernel(const float* __restrict__ xc, const float* __restrict__ xw,
                  float* __restrict__ proj)
{
    int t = blockIdx.x;
    int warp = threadIdx.x >> 5, lane = threadIdx.x & 31;
    const float* xr = xc + (size_t)t * DIN;
    float acc0 = 0, acc1 = 0, acc2 = 0, acc3 = 0;
    const float* w0 = xw + (size_t)(warp * 4 + 0) * DIN;
    const float* w1 = xw + (size_t)(warp * 4 + 1) * DIN;
    const float* w2 = xw + (size_t)(warp * 4 + 2) * DIN;
    const float* w3 = xw + (size_t)(warp * 4 + 3) * DIN;
    for (int k = lane; k < DIN; k += 32) {
        float xv = xr[k];
        acc0 = fmaf(xv, w0[k], acc0);
        acc1 = fmaf(xv, w1[k], acc1);
        acc2 = fmaf(xv, w2[k], acc2);
        acc3 = fmaf(xv, w3[k], acc3);
    }
#pragma unroll
    for (int o = 16; o > 0; o >>= 1) {
        acc0 += __shfl_xor_sync(0xffffffffu, acc0, o);
        acc1 += __shfl_xor_sync(0xffffffffu, acc1, o);
        acc2 += __shfl_xor_sync(0xffffffffu, acc2, o);
        acc3 += __shfl_xor_sync(0xffffffffu, acc3, o);
    }
    if (lane == 0) {
        proj[t * 32 + warp * 4 + 0] = acc0;
        proj[t * 32 + warp * 4 + 1] = acc1;
        proj[t * 32 + warp * 4 + 2] = acc2;
        proj[t * 32 + warp * 4 + 3] = acc3;
    }
}

// ---------------- dt ----------------
__global__ void dt_kernel(const float* __restrict__ proj, const float* __restrict__ dtw,
                          const float* __restrict__ dtb, float* __restrict__ dt)
{
    int t  = blockIdx.x >> 3;
    int d  = ((blockIdx.x & 7) << 8) + threadIdx.x;
    __shared__ float Bs[16];
    if (threadIdx.x < 16) Bs[threadIdx.x] = proj[t * 32 + threadIdx.x];
    __syncthreads();
    const float4* wp = (const float4*)(dtw + (size_t)d * 16);
    float4 w0 = wp[0], w1 = wp[1], w2 = wp[2], w3 = wp[3];
    float acc = dtb[d];
    acc = fmaf(Bs[0],  w0.x, acc); acc = fmaf(Bs[1],  w0.y, acc);
    acc = fmaf(Bs[2],  w0.z, acc); acc = fmaf(Bs[3],  w0.w, acc);
    acc = fmaf(Bs[4],  w1.x, acc); acc = fmaf(Bs[5],  w1.y, acc);
    acc = fmaf(Bs[6],  w1.z, acc); acc = fmaf(Bs[7],  w1.w, acc);
    acc = fmaf(Bs[8],  w2.x, acc); acc = fmaf(Bs[9],  w2.y, acc);
    acc = fmaf(Bs[10], w2.z, acc); acc = fmaf(Bs[11], w2.w, acc);
    acc = fmaf(Bs[12], w3.x, acc); acc = fmaf(Bs[13], w3.y, acc);
    acc = fmaf(Bs[14], w3.z, acc); acc = fmaf(Bs[15], w3.w, acc);
    dt[(size_t)t * DIN + d] = softplusf_(softplusf_(acc));
}

// ---------------- selective scan (4-t batched reductions) ----------------
__global__ __launch_bounds__(256)
void scan_kernel(const float* __restrict__ dt, const float* __restrict__ xc,
                 const float* __restrict__ proj, const float* __restrict__ Dp,
                 float* __restrict__ y, int T)
{
    int gid = blockIdx.x * blockDim.x + threadIdx.x;
    int d = gid >> 4;
    int s = gid & 15;
    const float A = -(float)(s + 1);
    const float Dd = Dp[d];
    float h = 0.0f;
    for (int t0 = 0; t0 < T; t0 += 4) {
        float v[4], xcv[4];
        float dtv[4], Bv[4], Cv[4];
#pragma unroll
        for (int j = 0; j < 4; j++) {
            int t = t0 + j;
            dtv[j] = dt[(size_t)t * DIN + d];
            xcv[j] = xc[(size_t)t * DIN + d];
            Bv[j]  = proj[t * 32 + s];
            Cv[j]  = proj[t * 32 + 16 + s];
        }
#pragma unroll
        for (int j = 0; j < 4; j++) {
            float da  = fmaxf(expf(dtv[j] * A), 1e-38f);
            float dbx = fmaxf(dtv[j] * Bv[j] * xcv[j], 1e-38f);
            h = fmaf(da, h, dbx);
            v[j] = Cv[j] * h;
        }
#pragma unroll
        for (int o = 8; o > 0; o >>= 1) {
            v[0] += __shfl_xor_sync(0xffffffffu, v[0], o, 16);
            v[1] += __shfl_xor_sync(0xffffffffu, v[1], o, 16);
            v[2] += __shfl_xor_sync(0xffffffffu, v[2], o, 16);
            v[3] += __shfl_xor_sync(0xffffffffu, v[3], o, 16);
        }
        if (s == 0) {
#pragma unroll
            for (int j = 0; j < 4; j++)
                y[(size_t)(t0 + j) * DIN + d] = v[j] + Dd * xcv[j];
        }
    }
}

// ---------------- fuse: fused fp32 + ctx hi/lo bf16 ----------------
__global__ void fuse_kernel(const float* __restrict__ y0, const float* __restrict__ y1,
                            const float* __restrict__ y2, const float* __restrict__ sw,
                            float* __restrict__ fused,
                            __nv_bfloat16* __restrict__ ctxh, __nv_bfloat16* __restrict__ ctxl)
{
    int idx = blockIdx.x * blockDim.x + threadIdx.x;
    int t = idx >> 11, d = idx & 2047;

    float o0 = y0[idx];

    float p1 = fminf(fmaxf(0.5f * (float)t - 0.25f, 0.0f), 511.0f);
    int lo1 = (int)floorf(p1);
    int hi1 = min(lo1 + 1, 511);
    float w1 = p1 - (float)lo1;
    float o1 = y1[(size_t)lo1 * DIN + d] * (1.0f - w1) + y1[(size_t)hi1 * DIN + d] * w1;

    float p2 = fminf(fmaxf(0.25f * (float)t - 0.375f, 0.0f), 255.0f);
    int lo2 = (int)floorf(p2);
    int hi2 = min(lo2 + 1, 255);
    float w2 = p2 - (float)lo2;
    float o2 = y2[(size_t)lo2 * DIN + d] * (1.0f - w2) + y2[(size_t)hi2 * DIN + d] * w2;

    float s0 = sw[0], s1 = sw[1], s2 = sw[2];
    float m = fmaxf(s0, fmaxf(s1, s2));
    float e0 = expf(s0 - m), e1 = expf(s1 - m), e2 = expf(s2 - m);
    float inv = 1.0f / (e0 + e1 + e2);

    fused[idx] = e0 * inv * o0 + e1 * inv * o1 + e2 * inv * o2;
    float cv = (o0 + o1 + o2) * (1.0f / 3.0f);
    __nv_bfloat16 h = __float2bfloat16_rn(cv);
    ctxh[idx] = h;
    ctxl[idx] = __float2bfloat16_rn(cv - __bfloat162float(h));
}

// ---------------- pre ----------------
__global__ void pre_kernel(const float* __restrict__ fused, const float* __restrict__ gc,
                           const float* __restrict__ xz,
                           __nv_bfloat16* __restrict__ preh, __nv_bfloat16* __restrict__ prel)
{
    int idx = blockIdx.x * blockDim.x + threadIdx.x;
    int t = idx >> 11, d = idx & 2047;
    float gv = xz[(size_t)t * 4096 + 2048 + d];
    float v = fused[idx] * gc[idx] * siluf_(gv);
    __nv_bfloat16 h = __float2bfloat16_rn(v);
    preh[idx] = h;
    prel[idx] = __float2bfloat16_rn(v - __bfloat162float(h));
}

// ---------------- layernorm ----------------
__global__ __launch_bounds__(256)
void ln_kernel(const float* __restrict__ y, const float* __restrict__ g,
               const float* __restrict__ b, float* __restrict__ out)
{
    int t = blockIdx.x;
    const float* yr = y + (size_t)t * DIMP;
    float vals[4];
    float s = 0.0f, s2 = 0.0f;
#pragma unroll
    for (int i = 0; i < 4; i++) {
        float v = yr[threadIdx.x + i * 256];
        vals[i] = v; s += v; s2 += v * v;
    }
#pragma unroll
    for (int o = 16; o > 0; o >>= 1) {
        s  += __shfl_xor_sync(0xffffffffu, s, o);
        s2 += __shfl_xor_sync(0xffffffffu, s2, o);
    }
    __shared__ float rs[8], rs2[8];
    int warp = threadIdx.x >> 5, lane = threadIdx.x & 31;
    if (lane == 0) { rs[warp] = s; rs2[warp] = s2; }
    __syncthreads();
    if (threadIdx.x == 0) {
        float S = 0, S2 = 0;
#pragma unroll
        for (int i = 0; i < 8; i++) { S += rs[i]; S2 += rs2[i]; }
        rs[0] = S; rs2[0] = S2;
    }
    __syncthreads();
    float mu  = rs[0] * (1.0f / 1024.0f);
    float var = rs2[0] * (1.0f / 1024.0f) - mu * mu;
    float rstd = rsqrtf(var + 1e-5f);
#pragma unroll
    for (int i = 0; i < 4; i++) {
        int j = threadIdx.x + i * 256;
        out[(size_t)t * DIMP + j] = (vals[i] - mu) * rstd * g[j] + b[j];
    }
}

// ---------------- launch ------------------------------------------------------
extern "C" void kernel_launch(void* const* d_in, const int* in_sizes, int n_in,
                              void* d_out, int out_size)
{
    const float* x          = (const float*)d_in[0];
    const float* in_proj_w  = (const float*)d_in[1];
    const float* conv_w     = (const float*)d_in[2];
    const float* conv_b     = (const float*)d_in[3];
    const float* xproj_w    = (const float*)d_in[4];
    const float* dtproj_w   = (const float*)d_in[5];
    const float* dtproj_b   = (const float*)d_in[6];
    const float* D_param    = (const float*)d_in[7];
    const float* scale_w    = (const float*)d_in[8];
    const float* gate_w1    = (const float*)d_in[9];
    const float* gate_w2    = (const float*)d_in[10];
    const float* out_proj_w = (const float*)d_in[11];
    const float* ln_g       = (const float*)d_in[12];
    const float* ln_b       = (const float*)d_in[13];
    float* out = (float*)d_out;

    float *xz, *x1, *x2, *xc, *proj, *dt, *yb, *fused, *gc, *yres;
    cudaGetSymbolAddress((void**)&xz,   g_xz);
    cudaGetSymbolAddress((void**)&x1,   g_x1);
    cudaGetSymbolAddress((void**)&x2,   g_x2);
    cudaGetSymbolAddress((void**)&xc,   g_xc);
    cudaGetSymbolAddress((void**)&proj, g_proj);
    cudaGetSymbolAddress((void**)&dt,   g_dt);
    cudaGetSymbolAddress((void**)&yb,   g_y);
    cudaGetSymbolAddress((void**)&fused,g_fused);
    cudaGetSymbolAddress((void**)&gc,   g_gc);
    cudaGetSymbolAddress((void**)&yres, g_yres);

    __nv_bfloat16 *xh,*xl,*w0h,*w0l,*ctxh,*ctxl,*w1h,*w1l,*g1h,*g1l,*w2h,*w2l,*preh,*prel,*w3h,*w3l;
    cudaGetSymbolAddress((void**)&xh,  g_xh);   cudaGetSymbolAddress((void**)&xl,  g_xl);
    cudaGetSymbolAddress((void**)&w0h, g_w0h);  cudaGetSymbolAddress((void**)&w0l, g_w0l);
    cudaGetSymbolAddress((void**)&ctxh,g_ctxh); cudaGetSymbolAddress((void**)&ctxl,g_ctxl);
    cudaGetSymbolAddress((void**)&w1h, g_w1h);  cudaGetSymbolAddress((void**)&w1l, g_w1l);
    cudaGetSymbolAddress((void**)&g1h, g_g1h);  cudaGetSymbolAddress((void**)&g1l, g_g1l);
    cudaGetSymbolAddress((void**)&w2h, g_w2h);  cudaGetSymbolAddress((void**)&w2l, g_w2l);
    cudaGetSymbolAddress((void**)&preh,g_preh); cudaGetSymbolAddress((void**)&prel,g_prel);
    cudaGetSymbolAddress((void**)&w3h, g_w3h);  cudaGetSymbolAddress((void**)&w3l, g_w3l);

    constexpr int SM128 = (2 * (2 * 128 * GPAD + 2 * 128 * GPAD)) * 2;  // 81920 B
    constexpr int SM64  = (2 * (2 * 64  * GPAD + 2 * 128 * GPAD)) * 2;  // 61440 B
    cudaFuncSetAttribute(gemm_mma<0,128>, cudaFuncAttributeMaxDynamicSharedMemorySize, SM128);
    cudaFuncSetAttribute(gemm_mma<1,64>,  cudaFuncAttributeMaxDynamicSharedMemorySize, SM64);
    cudaFuncSetAttribute(gemm_mma<2,64>,  cudaFuncAttributeMaxDynamicSharedMemorySize, SM64);
    cudaFuncSetAttribute(gemm_mma<3,64>,  cudaFuncAttributeMaxDynamicSharedMemorySize, SM64);

    // 0) preconvert x + all weights to bf16 hi/lo
    cvt_hilo_kernel<<<(TLEN*DIMP/4)/256, 256>>>(x, xh, xl);
    cvt_hilo_kernel<<<(4096*DIMP/4)/256, 256>>>(in_proj_w, w0h, w0l);
    cvt_hilo_kernel<<<(DIMP*DIN/4)/256, 256>>>(gate_w1, w1h, w1l);
    cvt_hilo_kernel<<<(DIN*DIMP/4)/256, 256>>>(gate_w2, w2h, w2l);
    cvt_hilo_kernel<<<(DIMP*DIN/4)/256, 256>>>(out_proj_w, w3h, w3l);

    // 1) xz = x @ in_proj_w^T   [1024,4096]
    gemm_mma<0,128><<<dim3(32, 8), 256, SM128>>>(xh, xl, w0h, w0l, xz, nullptr, nullptr, nullptr,
                                                 1024, 4096, 1024);

    // 2) downsample
    down2_kernel<<<(512 * DIN) / 256, 256>>>(xz, x1);
    down4_kernel<<<(256 * DIN) / 256, 256>>>(xz, x2);

    // 3) per-scale SSM
    const int   Ts[3]   = {1024, 512, 256};
    const int   toff[3] = {0, 1024, 1536};
    const int   xstr[3] = {4096, DIN, DIN};
    const float* xs[3]; xs[0] = xz; xs[1] = x1; xs[2] = x2;

    for (int s = 0; s < 3; s++) {
        float* xc_s   = xc   + (size_t)toff[s] * DIN;
        float* proj_s = proj + (size_t)toff[s] * 32;
        float* dt_s   = dt   + (size_t)toff[s] * DIN;
        float* y_s    = yb   + (size_t)toff[s] * DIN;

        conv_silu_kernel<<<(Ts[s] * DIN) / 256, 256>>>(
            xs[s], xstr[s], conv_w + (size_t)s * DIN * 4, conv_b + (size_t)s * DIN, xc_s, Ts[s]);
        xproj_kernel<<<Ts[s], 256>>>(xc_s, xproj_w + (size_t)s * 32 * DIN, proj_s);
        dt_kernel<<<Ts[s] * 8, 256>>>(proj_s, dtproj_w + (size_t)s * DIN * 16,
                                      dtproj_b + (size_t)s * DIN, dt_s);
        scan_kernel<<<(DIN * NSTATE) / 256, 256>>>(dt_s, xc_s, proj_s,
                                                   D_param + (size_t)s * DIN, y_s, Ts[s]);
    }

    // 4) fuse -> fused fp32, ctx hi/lo
    fuse_kernel<<<(TLEN * DIN) / 256, 256>>>(yb, yb + (size_t)1024 * DIN, yb + (size_t)1536 * DIN,
                                             scale_w, fused, ctxh, ctxl);

    // 5) gating
    gemm_mma<1,64><<<dim3(8, 16), 256, SM64>>>(ctxh, ctxl, w1h, w1l, nullptr, g1h, g1l, nullptr,
                                               1024, 1024, 2048);
    gemm_mma<2,64><<<dim3(16, 16), 256, SM64>>>(g1h, g1l, w2h, w2l, gc, nullptr, nullptr, nullptr,
                                                1024, 2048, 1024);

    // 6) pre
    pre_kernel<<<(TLEN * DIN) / 256, 256>>>(fused, gc, xz, preh, prel);

    // 7) out_proj + residual
    gemm_mma<3,64><<<dim3(8, 16), 256, SM64>>>(preh, prel, w3h, w3l, yres, nullptr, nullptr, x,
                                               1024, 1024, 2048);

    // 8) layernorm
    ln_kernel<<<1024, 256>>>(yres, ln_g, ln_b, out);
}